// round 5
// baseline (speedup 1.0000x reference)
#include <cuda_runtime.h>
#include <cuda_bf16.h>
#include <cstdint>
#include <math.h>

// ---------------- problem constants ----------------
#define T_TOK 2048
#define HDIM  2048
#define FDIM  5504
#define EEXP  8

// ---------------- device scratch (static, no allocation) ----------------
__device__ int   g_cnt[EEXP];
__device__ int   g_ptok[EEXP * T_TOK];
__device__ float g_pw[EEXP * T_TOK];

#define GAELEM ((size_t)EEXP * (size_t)T_TOK * (size_t)HDIM)
#define HBELEM ((size_t)EEXP * (size_t)T_TOK * (size_t)FDIM)
__device__ __align__(16) __nv_bfloat16 g_gah[GAELEM]; // gathered x hi
__device__ __align__(16) __nv_bfloat16 g_gal[GAELEM]; // gathered x lo
__device__ __align__(16) __nv_bfloat16 g_hbh[HBELEM]; // silu(g)*u hi
__device__ __align__(16) __nv_bfloat16 g_hbl[HBELEM]; // silu(g)*u lo

// ---------------- PTX helpers ----------------
__device__ __forceinline__ uint32_t smem_u32(const void* p) {
    uint32_t a;
    asm("{ .reg .u64 t; cvta.to.shared.u64 t, %1; cvt.u32.u64 %0, t; }"
        : "=r"(a) : "l"(p));
    return a;
}

__device__ __forceinline__ void cpa16(uint32_t dst, const void* src) {
    asm volatile("cp.async.cg.shared.global [%0], [%1], 16;"
                 :: "r"(dst), "l"(src) : "memory");
}
#define CPA_COMMIT() asm volatile("cp.async.commit_group;" ::: "memory")
#define CPA_WAIT0()  asm volatile("cp.async.wait_group 0;" ::: "memory")
#define FENCE_ASYNC() asm volatile("fence.proxy.async.shared::cta;" ::: "memory")

#define MBAR_INIT(addr, cnt) \
    asm volatile("mbarrier.init.shared.b64 [%0], %1;" :: "r"(addr), "r"(cnt) : "memory")
#define MBAR_ARRIVE(addr) \
    asm volatile("mbarrier.arrive.shared.b64 _, [%0];" :: "r"(addr) : "memory")
#define MBAR_WAIT(addr, par) do {                                             \
    uint32_t _m = (addr); uint32_t _p = (par); uint32_t _d;                   \
    asm volatile("{\n\t.reg .pred p;\n\t"                                     \
        "mbarrier.try_wait.parity.shared.b64 p, [%1], %2;\n\t"                \
        "selp.b32 %0, 1, 0, p;\n\t}"                                          \
        : "=r"(_d) : "r"(_m), "r"(_p) : "memory");                            \
    if (!_d) {                                                                \
        asm volatile("{\n\t.reg .pred P1;\n\t"                                \
            "WL_%=:\n\t"                                                      \
            "mbarrier.try_wait.parity.shared.b64 P1, [%0], %1;\n\t"           \
            "@P1 bra.uni WD_%=;\n\t"                                          \
            "bra.uni WL_%=;\n\t"                                              \
            "WD_%=:\n\t}"                                                     \
            :: "r"(_m), "r"(_p) : "memory");                                  \
    }                                                                         \
} while (0)

__device__ __forceinline__ void ldsm4(uint32_t* r, uint32_t addr) {
    asm volatile("ldmatrix.sync.aligned.m8n8.x4.shared.b16 {%0,%1,%2,%3}, [%4];"
                 : "=r"(r[0]), "=r"(r[1]), "=r"(r[2]), "=r"(r[3]) : "r"(addr));
}

__device__ __forceinline__ void mma16816(float* c, const uint32_t* a, const uint32_t* b) {
    asm volatile(
        "mma.sync.aligned.m16n8k16.row.col.f32.bf16.bf16.f32 "
        "{%0,%1,%2,%3}, {%4,%5,%6,%7}, {%8,%9}, {%0,%1,%2,%3};"
        : "+f"(c[0]), "+f"(c[1]), "+f"(c[2]), "+f"(c[3])
        : "r"(a[0]), "r"(a[1]), "r"(a[2]), "r"(a[3]), "r"(b[0]), "r"(b[1]));
}

// hi/lo split of 4 floats -> bf16 hi/lo pairs (gmem)
__device__ __forceinline__ void split4(float4 v,
                                       __nv_bfloat16* __restrict__ hi,
                                       __nv_bfloat16* __restrict__ lo,
                                       size_t i) {
    __nv_bfloat162 h0 = __floats2bfloat162_rn(v.x, v.y);
    __nv_bfloat162 h1 = __floats2bfloat162_rn(v.z, v.w);
    *(__nv_bfloat162*)(hi + i)     = h0;
    *(__nv_bfloat162*)(hi + i + 2) = h1;
    __nv_bfloat162 l0, l1;
    l0.x = __float2bfloat16_rn(v.x - __bfloat162float(h0.x));
    l0.y = __float2bfloat16_rn(v.y - __bfloat162float(h0.y));
    l1.x = __float2bfloat16_rn(v.z - __bfloat162float(h1.x));
    l1.y = __float2bfloat16_rn(v.w - __bfloat162float(h1.y));
    *(__nv_bfloat162*)(lo + i)     = l0;
    *(__nv_bfloat162*)(lo + i + 2) = l1;
}

// split 4 floats and store hi (8B) + lo (8B) into smem
__device__ __forceinline__ void split_sts(char* sm, uint32_t off, float4 v) {
    __nv_bfloat162 h0 = __floats2bfloat162_rn(v.x, v.y);
    __nv_bfloat162 h1 = __floats2bfloat162_rn(v.z, v.w);
    uint2 hp = make_uint2(*(uint32_t*)&h0, *(uint32_t*)&h1);
    *(uint2*)(sm + off) = hp;
    __nv_bfloat162 l0, l1;
    l0.x = __float2bfloat16_rn(v.x - __bfloat162float(h0.x));
    l0.y = __float2bfloat16_rn(v.y - __bfloat162float(h0.y));
    l1.x = __float2bfloat16_rn(v.z - __bfloat162float(h1.x));
    l1.y = __float2bfloat16_rn(v.w - __bfloat162float(h1.y));
    uint2 lp = make_uint2(*(uint32_t*)&l0, *(uint32_t*)&l1);
    *(uint2*)(sm + off + 16384) = lp;
}

// ---------------- kernel 0: zero counters ----------------
__global__ void zero_cnt_kernel() {
    if (threadIdx.x < EEXP) g_cnt[threadIdx.x] = 0;
}

// ---------------- kernel 1: router ----------------
__global__ void __launch_bounds__(256) router_kernel(const float* __restrict__ x,
                                                     const float* __restrict__ rw) {
    int t = blockIdx.x;
    int warp = threadIdx.x >> 5;
    int lane = threadIdx.x & 31;
    __shared__ float logits[EEXP];

    const float* xr = x + (size_t)t * HDIM;
    const float* wr = rw + (size_t)warp * HDIM;
    float s = 0.f;
    for (int h = lane * 4; h < HDIM; h += 128) {
        float4 xv = *(const float4*)(xr + h);
        float4 wv = *(const float4*)(wr + h);
        s = fmaf(xv.x, wv.x, s);
        s = fmaf(xv.y, wv.y, s);
        s = fmaf(xv.z, wv.z, s);
        s = fmaf(xv.w, wv.w, s);
    }
    #pragma unroll
    for (int o = 16; o; o >>= 1) s += __shfl_down_sync(0xffffffffu, s, o);
    if (lane == 0) logits[warp] = s;
    __syncthreads();

    if (threadIdx.x == 0) {
        int i0 = 0; float v0 = logits[0];
        #pragma unroll
        for (int i = 1; i < EEXP; i++)
            if (logits[i] > v0) { v0 = logits[i]; i0 = i; }
        int i1 = -1; float v1 = -3.0e38f;
        #pragma unroll
        for (int i = 0; i < EEXP; i++) {
            if (i == i0) continue;
            if (logits[i] > v1) { v1 = logits[i]; i1 = i; }
        }
        float e1 = expf(v1 - v0);
        float inv = 1.f / (1.f + e1);
        int s0 = atomicAdd(&g_cnt[i0], 1);
        g_ptok[i0 * T_TOK + s0] = t;
        g_pw  [i0 * T_TOK + s0] = inv;
        int s1 = atomicAdd(&g_cnt[i1], 1);
        g_ptok[i1 * T_TOK + s1] = t;
        g_pw  [i1 * T_TOK + s1] = e1 * inv;
    }
}

// ---------------- kernel 2: gather tokens + bf16 hi/lo split ----------------
__global__ void __launch_bounds__(128) gather_x_kernel(const float* __restrict__ x) {
    int row = blockIdx.x;                 // e*T_TOK + slot
    int e = row >> 11;
    int slot = row & (T_TOK - 1);
    if (slot >= g_cnt[e]) return;
    const float4* src = (const float4*)(x + (size_t)g_ptok[row] * HDIM);
    size_t ob = (size_t)row * HDIM;
    for (int i = threadIdx.x; i < HDIM / 4; i += 128)
        split4(src[i], g_gah, g_gal, ob + (size_t)i * 4);
}

// ---------------- GEMM pipeline layout ----------------
// stage (64KB): A hi 16K @0 | A lo 16K @16384 | B hi 16K @32768 | B lo 16K @49152
// 3 stages = 196608 B; barriers: full[3] @196608+, empty[3] @196632+
#define STGSZ  65536u
#define NST    3
#define BAR_OFF 196608u
#define SMEM_GEMM 196864

// two k16 steps of the 3-pass bf16x3 MMA over a 64x32 warp tile
__device__ __forceinline__ void mma_half(uint32_t Ab, uint32_t Bb, int kk0,
                                         int wm, int wn, int lane,
                                         float (&acc)[4][4][4]) {
    #pragma unroll
    for (int ks = 0; ks < 2; ks++) {
        int kk = kk0 + ks * 16;
        uint32_t ah[4][4], al[4][4], bh[4][2], bl[4][2];
        int lrow = lane & 15;
        int au = (kk >> 3) + (lane >> 4);          // A smem unit
        #pragma unroll
        for (int mi = 0; mi < 4; mi++) {
            int r = wm * 64 + mi * 16 + lrow;
            uint32_t ad = Ab + r * 128 + ((au ^ (r & 7)) << 4);
            ldsm4(ah[mi], ad);
            ldsm4(al[mi], ad + 16384);
        }
        int bu = (kk >> 3) + ((lane >> 3) & 1);    // B smem unit
        #pragma unroll
        for (int bi = 0; bi < 2; bi++) {
            int nr = wn * 32 + bi * 16 + ((lane >> 4) << 3) + (lane & 7);
            uint32_t bd = Bb + nr * 128 + ((bu ^ (nr & 7)) << 4);
            uint32_t t[4];
            ldsm4(t, bd);
            bh[2 * bi][0] = t[0]; bh[2 * bi][1] = t[1];
            bh[2 * bi + 1][0] = t[2]; bh[2 * bi + 1][1] = t[3];
            ldsm4(t, bd + 16384);
            bl[2 * bi][0] = t[0]; bl[2 * bi][1] = t[1];
            bl[2 * bi + 1][0] = t[2]; bl[2 * bi + 1][1] = t[3];
        }
        #pragma unroll
        for (int mi = 0; mi < 4; mi++)
            #pragma unroll
            for (int ni = 0; ni < 4; ni++) {
                mma16816(acc[mi][ni], ah[mi], bh[ni]);
                mma16816(acc[mi][ni], al[mi], bh[ni]);
                mma16816(acc[mi][ni], ah[mi], bl[ni]);
            }
    }
}

// producer: A tile via cp.async (hi/lo), 16 units x 2 per thread
__device__ __forceinline__ void prod_A(uint32_t base,
                                       const __nv_bfloat16* __restrict__ Ahi,
                                       const __nv_bfloat16* __restrict__ Alo,
                                       size_t stride, int k0, int pt) {
    #pragma unroll
    for (int i = 0; i < 16; i++) {
        int flat = pt + (i << 6);
        int r = flat >> 3, u = flat & 7;
        uint32_t dst = base + r * 128 + ((u ^ (r & 7)) << 4);
        size_t off = (size_t)r * stride + k0 + u * 8;
        cpa16(dst, Ahi + off);
        cpa16(dst + 16384, Alo + off);
    }
}

// ---------------- kernel 3: gate/up GEMM + SiLU (warp-specialized) ----------------
// 320 threads: warps 0-7 MMA, warps 8-9 producers.
__global__ void __launch_bounds__(320, 1) gemm1_kernel(const float* __restrict__ gw,
                                                       const float* __restrict__ uw) {
    extern __shared__ char sm[];
    uint32_t sb = smem_u32(sm);
    int e = blockIdx.z;
    int cnt = g_cnt[e];
    int m0 = blockIdx.x << 7;
    if (m0 >= cnt) return;
    int n0f = blockIdx.y << 6;
    int tid = threadIdx.x, lane = tid & 31, wid = tid >> 5;
    const int NC = HDIM / 64;   // 32

    if (tid == 0) {
        #pragma unroll
        for (int s = 0; s < NST; s++) {
            MBAR_INIT(sb + BAR_OFF + s * 8, 2);       // full: 2 producer warps
            MBAR_INIT(sb + BAR_OFF + 24 + s * 8, 8);  // empty: 8 MMA warps
        }
    }
    __syncthreads();

    if (wid >= 8) {
        // -------------------- producers --------------------
        int pt = tid - 256;   // 0..63
        const __nv_bfloat16* Ahi = g_gah + ((size_t)e * T_TOK + m0) * HDIM;
        const __nv_bfloat16* Alo = g_gal + ((size_t)e * T_TOK + m0) * HDIM;
        const float* gwB = gw + ((size_t)e * FDIM + n0f) * HDIM;
        const float* uwB = uw + ((size_t)e * FDIM + n0f) * HDIM;
        int s = 0, ph = 1;
        for (int c = 0; c < NC; c++) {
            MBAR_WAIT(sb + BAR_OFF + 24 + s * 8, ph);
            uint32_t base = sb + s * STGSZ;
            char* smb = sm + s * STGSZ;
            int k0 = c << 6;
            prod_A(base, Ahi, Alo, HDIM, k0, pt);
            CPA_COMMIT();
            // B: 128 interleaved rows (gate even / up odd) x 64 k, fp32 -> hi/lo
            #pragma unroll
            for (int i = 0; i < 32; i++) {
                int flat = pt + (i << 6);
                int row = flat >> 4, c4 = flat & 15;
                const float* src = (row < 64) ? (gwB + (size_t)row * HDIM)
                                              : (uwB + (size_t)(row - 64) * HDIM);
                float4 v = *(const float4*)(src + k0 + c4 * 4);
                int sr = (row < 64) ? (row << 1) : (((row - 64) << 1) + 1);
                uint32_t off = 32768u + sr * 128 + (((c4 >> 1) ^ (sr & 7)) << 4) + ((c4 & 1) << 3);
                split_sts(smb, off, v);
            }
            CPA_WAIT0();
            FENCE_ASYNC();
            __syncwarp();
            if (lane == 0) MBAR_ARRIVE(sb + BAR_OFF + s * 8);
            if (++s == NST) { s = 0; ph ^= 1; }
        }
        return;
    }

    // -------------------- MMA warps --------------------
    int wm = wid & 1, wn = wid >> 1;
    float acc[4][4][4];
    #pragma unroll
    for (int a = 0; a < 4; a++)
        #pragma unroll
        for (int b = 0; b < 4; b++)
            #pragma unroll
            for (int c = 0; c < 4; c++) acc[a][b][c] = 0.f;

    int s = 0, ph = 0;
    for (int c = 0; c < NC; c++) {
        MBAR_WAIT(sb + BAR_OFF + s * 8, ph);
        uint32_t Ab = sb + s * STGSZ;
        uint32_t Bb = Ab + 32768u;
        mma_half(Ab, Bb, 0, wm, wn, lane, acc);
        mma_half(Ab, Bb, 32, wm, wn, lane, acc);
        __syncwarp();
        if (lane == 0) MBAR_ARRIVE(sb + BAR_OFF + 24 + s * 8);
        if (++s == NST) { s = 0; ph ^= 1; }
    }

    // epilogue: cols 2j/2j+1 = (gate_j, up_j); h = silu(g)*u -> hi/lo bf16
    #pragma unroll
    for (int mi = 0; mi < 4; mi++)
        #pragma unroll
        for (int rh = 0; rh < 2; rh++) {
            int row = wm * 64 + mi * 16 + (lane >> 2) + rh * 8;
            int slot = m0 + row;
            if (slot < cnt) {
                size_t hb = ((size_t)e * T_TOK + slot) * FDIM + n0f;
                #pragma unroll
                for (int ni = 0; ni < 4; ni++) {
                    float g = acc[mi][ni][rh * 2 + 0];
                    float u = acc[mi][ni][rh * 2 + 1];
                    float h = u * g / (1.f + __expf(-g));
                    int j = wn * 16 + ni * 4 + (lane & 3);
                    __nv_bfloat16 hh = __float2bfloat16_rn(h);
                    g_hbh[hb + j] = hh;
                    g_hbl[hb + j] = __float2bfloat16_rn(h - __bfloat162float(hh));
                }
            }
        }
}

// ---------------- kernel 4: down GEMM + weighted scatter (warp-specialized) ----------------
__global__ void __launch_bounds__(320, 1) gemm2_kernel(const float* __restrict__ dw,
                                                       float* __restrict__ out) {
    extern __shared__ char sm[];
    uint32_t sb = smem_u32(sm);
    int e = blockIdx.z;
    int cnt = g_cnt[e];
    int m0 = blockIdx.x << 7;
    if (m0 >= cnt) return;
    int n0 = blockIdx.y << 7;
    int tid = threadIdx.x, lane = tid & 31, wid = tid >> 5;
    const int NC = FDIM / 64;   // 86

    if (tid == 0) {
        #pragma unroll
        for (int s = 0; s < NST; s++) {
            MBAR_INIT(sb + BAR_OFF + s * 8, 2);
            MBAR_INIT(sb + BAR_OFF + 24 + s * 8, 8);
        }
    }
    __syncthreads();

    if (wid >= 8) {
        int pt = tid - 256;
        const __nv_bfloat16* Ahi = g_hbh + ((size_t)e * T_TOK + m0) * FDIM;
        const __nv_bfloat16* Alo = g_hbl + ((size_t)e * T_TOK + m0) * FDIM;
        const float* dwB = dw + ((size_t)e * HDIM + n0) * FDIM;
        int s = 0, ph = 1;
        for (int c = 0; c < NC; c++) {
            MBAR_WAIT(sb + BAR_OFF + 24 + s * 8, ph);
            uint32_t base = sb + s * STGSZ;
            char* smb = sm + s * STGSZ;
            int k0 = c << 6;
            prod_A(base, Ahi, Alo, FDIM, k0, pt);
            CPA_COMMIT();
            #pragma unroll
            for (int i = 0; i < 32; i++) {
                int flat = pt + (i << 6);
                int row = flat >> 4, c4 = flat & 15;
                float4 v = *(const float4*)(dwB + (size_t)row * FDIM + k0 + c4 * 4);
                uint32_t off = 32768u + row * 128 + (((c4 >> 1) ^ (row & 7)) << 4) + ((c4 & 1) << 3);
                split_sts(smb, off, v);
            }
            CPA_WAIT0();
            FENCE_ASYNC();
            __syncwarp();
            if (lane == 0) MBAR_ARRIVE(sb + BAR_OFF + s * 8);
            if (++s == NST) { s = 0; ph ^= 1; }
        }
        return;
    }

    int wm = wid & 1, wn = wid >> 1;
    float acc[4][4][4];
    #pragma unroll
    for (int a = 0; a < 4; a++)
        #pragma unroll
        for (int b = 0; b < 4; b++)
            #pragma unroll
            for (int c = 0; c < 4; c++) acc[a][b][c] = 0.f;

    int s = 0, ph = 0;
    for (int c = 0; c < NC; c++) {
        MBAR_WAIT(sb + BAR_OFF + s * 8, ph);
        uint32_t Ab = sb + s * STGSZ;
        uint32_t Bb = Ab + 32768u;
        mma_half(Ab, Bb, 0, wm, wn, lane, acc);
        mma_half(Ab, Bb, 32, wm, wn, lane, acc);
        __syncwarp();
        if (lane == 0) MBAR_ARRIVE(sb + BAR_OFF + 24 + s * 8);
        if (++s == NST) { s = 0; ph ^= 1; }
    }

    // epilogue: weighted atomic scatter to out
    #pragma unroll
    for (int mi = 0; mi < 4; mi++)
        #pragma unroll
        for (int rh = 0; rh < 2; rh++) {
            int row = wm * 64 + mi * 16 + (lane >> 2) + rh * 8;
            int slot = m0 + row;
            if (slot < cnt) {
                int tok = g_ptok[e * T_TOK + slot];
                float w = g_pw[e * T_TOK + slot];
                float* orow = out + (size_t)tok * HDIM + n0;
                #pragma unroll
                for (int ni = 0; ni < 4; ni++) {
                    int col = wn * 32 + ni * 8 + 2 * (lane & 3);
                    atomicAdd(orow + col,     acc[mi][ni][rh * 2 + 0] * w);
                    atomicAdd(orow + col + 1, acc[mi][ni][rh * 2 + 1] * w);
                }
            }
        }
}

// ---------------- launch ----------------
extern "C" void kernel_launch(void* const* d_in, const int* in_sizes, int n_in,
                              void* d_out, int out_size) {
    const float* x  = (const float*)d_in[0];   // [B,S,H]
    const float* rw = (const float*)d_in[1];   // [E,H]
    const float* gw = (const float*)d_in[2];   // [E,F,H]
    const float* uw = (const float*)d_in[3];   // [E,F,H]
    const float* dw = (const float*)d_in[4];   // [E,H,F]
    float* out = (float*)d_out;

    cudaFuncSetAttribute(gemm1_kernel, cudaFuncAttributeMaxDynamicSharedMemorySize, SMEM_GEMM);
    cudaFuncSetAttribute(gemm2_kernel, cudaFuncAttributeMaxDynamicSharedMemorySize, SMEM_GEMM);

    cudaMemsetAsync(out, 0, (size_t)out_size * sizeof(float));
    zero_cnt_kernel<<<1, 32>>>();
    router_kernel<<<T_TOK, 256>>>(x, rw);
    gather_x_kernel<<<EEXP * T_TOK, 128>>>(x);
    gemm1_kernel<<<dim3(16, FDIM / 64, EEXP), 320, SMEM_GEMM>>>(gw, uw);
    gemm2_kernel<<<dim3(16, HDIM / 128, EEXP), 320, SMEM_GEMM>>>(dw, out);
}

// round 7
// speedup vs baseline: 3.0089x; 3.0089x over previous
#include <cuda_runtime.h>
#include <cuda_bf16.h>
#include <cstdint>
#include <math.h>

// ---------------- problem constants ----------------
#define T_TOK 2048
#define HDIM  2048
#define FDIM  5504
#define EEXP  8

// ---------------- device scratch (static, no allocation) ----------------
__device__ int   g_cnt[EEXP];
__device__ int   g_ptok[EEXP * T_TOK];
__device__ float g_pw[EEXP * T_TOK];

#define GAELEM ((size_t)EEXP * (size_t)T_TOK * (size_t)HDIM)
#define HBELEM ((size_t)EEXP * (size_t)T_TOK * (size_t)FDIM)
__device__ __align__(16) __nv_bfloat16 g_gah[GAELEM]; // gathered x hi
__device__ __align__(16) __nv_bfloat16 g_gal[GAELEM]; // gathered x lo
__device__ __align__(16) __nv_bfloat16 g_hbh[HBELEM]; // silu(g)*u hi
__device__ __align__(16) __nv_bfloat16 g_hbl[HBELEM]; // silu(g)*u lo

// ---------------- PTX helpers ----------------
__device__ __forceinline__ uint32_t smem_u32(const void* p) {
    uint32_t a;
    asm("{ .reg .u64 t; cvta.to.shared.u64 t, %1; cvt.u32.u64 %0, t; }"
        : "=r"(a) : "l"(p));
    return a;
}

__device__ __forceinline__ void cpa16(uint32_t dst, const void* src) {
    asm volatile("cp.async.cg.shared.global [%0], [%1], 16;"
                 :: "r"(dst), "l"(src) : "memory");
}

#define MBAR_INIT(addr, cnt) \
    asm volatile("mbarrier.init.shared.b64 [%0], %1;" :: "r"(addr), "r"(cnt) : "memory")
#define MBAR_ARRIVE(addr) \
    asm volatile("mbarrier.arrive.shared.b64 _, [%0];" :: "r"(addr) : "memory")
// arrive (counted against the INIT count: .noinc) on completion of this
// thread's prior cp.async ops
#define MBAR_CPA_ARRIVE(addr) \
    asm volatile("cp.async.mbarrier.arrive.noinc.shared.b64 [%0];" :: "r"(addr) : "memory")
#define MBAR_WAIT(addr, par) do {                                             \
    uint32_t _m = (addr); uint32_t _p = (par); uint32_t _d;                   \
    asm volatile("{\n\t.reg .pred p;\n\t"                                     \
        "mbarrier.try_wait.parity.shared.b64 p, [%1], %2;\n\t"                \
        "selp.b32 %0, 1, 0, p;\n\t}"                                          \
        : "=r"(_d) : "r"(_m), "r"(_p) : "memory");                            \
    if (!_d) {                                                                \
        asm volatile("{\n\t.reg .pred P1;\n\t"                                \
            "WL_%=:\n\t"                                                      \
            "mbarrier.try_wait.parity.shared.b64 P1, [%0], %1;\n\t"           \
            "@P1 bra.uni WD_%=;\n\t"                                          \
            "bra.uni WL_%=;\n\t"                                              \
            "WD_%=:\n\t}"                                                     \
            :: "r"(_m), "r"(_p) : "memory");                                  \
    }                                                                         \
} while (0)

__device__ __forceinline__ void ldsm4(uint32_t* r, uint32_t addr) {
    asm volatile("ldmatrix.sync.aligned.m8n8.x4.shared.b16 {%0,%1,%2,%3}, [%4];"
                 : "=r"(r[0]), "=r"(r[1]), "=r"(r[2]), "=r"(r[3]) : "r"(addr));
}

__device__ __forceinline__ void mma16816(float* c, const uint32_t* a, const uint32_t* b) {
    asm volatile(
        "mma.sync.aligned.m16n8k16.row.col.f32.bf16.bf16.f32 "
        "{%0,%1,%2,%3}, {%4,%5,%6,%7}, {%8,%9}, {%0,%1,%2,%3};"
        : "+f"(c[0]), "+f"(c[1]), "+f"(c[2]), "+f"(c[3])
        : "r"(a[0]), "r"(a[1]), "r"(a[2]), "r"(a[3]), "r"(b[0]), "r"(b[1]));
}

// hi/lo split of 4 floats -> bf16 hi/lo pairs (gmem)
__device__ __forceinline__ void split4(float4 v,
                                       __nv_bfloat16* __restrict__ hi,
                                       __nv_bfloat16* __restrict__ lo,
                                       size_t i) {
    __nv_bfloat162 h0 = __floats2bfloat162_rn(v.x, v.y);
    __nv_bfloat162 h1 = __floats2bfloat162_rn(v.z, v.w);
    *(__nv_bfloat162*)(hi + i)     = h0;
    *(__nv_bfloat162*)(hi + i + 2) = h1;
    __nv_bfloat162 l0, l1;
    l0.x = __float2bfloat16_rn(v.x - __bfloat162float(h0.x));
    l0.y = __float2bfloat16_rn(v.y - __bfloat162float(h0.y));
    l1.x = __float2bfloat16_rn(v.z - __bfloat162float(h1.x));
    l1.y = __float2bfloat16_rn(v.w - __bfloat162float(h1.y));
    *(__nv_bfloat162*)(lo + i)     = l0;
    *(__nv_bfloat162*)(lo + i + 2) = l1;
}

// ---------------- kernel 0: zero counters ----------------
__global__ void zero_cnt_kernel() {
    if (threadIdx.x < EEXP) g_cnt[threadIdx.x] = 0;
}

// ---------------- kernel 1: router ----------------
__global__ void __launch_bounds__(256) router_kernel(const float* __restrict__ x,
                                                     const float* __restrict__ rw) {
    int t = blockIdx.x;
    int warp = threadIdx.x >> 5;
    int lane = threadIdx.x & 31;
    __shared__ float logits[EEXP];

    const float* xr = x + (size_t)t * HDIM;
    const float* wr = rw + (size_t)warp * HDIM;
    float s = 0.f;
    for (int h = lane * 4; h < HDIM; h += 128) {
        float4 xv = *(const float4*)(xr + h);
        float4 wv = *(const float4*)(wr + h);
        s = fmaf(xv.x, wv.x, s);
        s = fmaf(xv.y, wv.y, s);
        s = fmaf(xv.z, wv.z, s);
        s = fmaf(xv.w, wv.w, s);
    }
    #pragma unroll
    for (int o = 16; o; o >>= 1) s += __shfl_down_sync(0xffffffffu, s, o);
    if (lane == 0) logits[warp] = s;
    __syncthreads();

    if (threadIdx.x == 0) {
        int i0 = 0; float v0 = logits[0];
        #pragma unroll
        for (int i = 1; i < EEXP; i++)
            if (logits[i] > v0) { v0 = logits[i]; i0 = i; }
        int i1 = -1; float v1 = -3.0e38f;
        #pragma unroll
        for (int i = 0; i < EEXP; i++) {
            if (i == i0) continue;
            if (logits[i] > v1) { v1 = logits[i]; i1 = i; }
        }
        float e1 = expf(v1 - v0);
        float inv = 1.f / (1.f + e1);
        int s0 = atomicAdd(&g_cnt[i0], 1);
        g_ptok[i0 * T_TOK + s0] = t;
        g_pw  [i0 * T_TOK + s0] = inv;
        int s1 = atomicAdd(&g_cnt[i1], 1);
        g_ptok[i1 * T_TOK + s1] = t;
        g_pw  [i1 * T_TOK + s1] = e1 * inv;
    }
}

// ---------------- kernel 2: gather tokens + bf16 hi/lo split ----------------
__global__ void __launch_bounds__(128) gather_x_kernel(const float* __restrict__ x) {
    int row = blockIdx.x;                 // e*T_TOK + slot
    int e = row >> 11;
    int slot = row & (T_TOK - 1);
    if (slot >= g_cnt[e]) return;
    const float4* src = (const float4*)(x + (size_t)g_ptok[row] * HDIM);
    size_t ob = (size_t)row * HDIM;
    for (int i = threadIdx.x; i < HDIM / 4; i += 128)
        split4(src[i], g_gah, g_gal, ob + (size_t)i * 4);
}

// ---------------- GEMM pipeline layout ----------------
// stage (64KB): A hi 16K @0 | A lo 16K @16384 | B hi 16K @32768 | B lo 16K @49152
// 3 stages; barriers @196608: full[3] (+0,8,16), empty[3] (+24,32,40)
#define STGSZ   65536u
#define NST     3
#define BAR_OFF 196608u
#define SMEM_GEMM 196864
#define BAR_FULL(sb, s)  ((sb) + BAR_OFF + (uint32_t)(s) * 8)
#define BAR_EMPTY(sb, s) ((sb) + BAR_OFF + 24 + (uint32_t)(s) * 8)

// cp.async a 128x64 bf16 hi/lo A tile into SW128-swizzled smem (256 threads)
__device__ __forceinline__ void cpa_tileA(uint32_t base,
                                          const __nv_bfloat16* __restrict__ hi,
                                          const __nv_bfloat16* __restrict__ lo,
                                          size_t stride, int k0, int tid) {
    #pragma unroll
    for (int i = 0; i < 4; i++) {
        int flat = tid + (i << 8);
        int r = flat >> 3, u = flat & 7;
        uint32_t dst = base + r * 128 + ((u ^ (r & 7)) << 4);
        size_t off = (size_t)r * stride + k0 + u * 8;
        cpa16(dst, hi + off);
        cpa16(dst + 16384, lo + off);
    }
}

// store fp32 regs as bf16 hi/lo into swizzled B tile (optionally interleaving
// gate/up rows: smem row = 2*r (gate) / 2*r+1 (up))
template <bool IL>
__device__ __forceinline__ void sts_B(char* sm, uint32_t sboff, const float4* br, int tid) {
    #pragma unroll
    for (int i = 0; i < 8; i++) {
        int flat = tid + (i << 8);
        int row = flat >> 4, c4 = flat & 15;
        int sr = IL ? ((row < 64) ? (row << 1) : (((row - 64) << 1) + 1)) : row;
        uint32_t off = sboff + sr * 128 + (((c4 >> 1) ^ (sr & 7)) << 4) + ((c4 & 1) << 3);
        float4 v = br[i];
        __nv_bfloat162 h0 = __floats2bfloat162_rn(v.x, v.y);
        __nv_bfloat162 h1 = __floats2bfloat162_rn(v.z, v.w);
        *(__nv_bfloat162*)(sm + off)     = h0;
        *(__nv_bfloat162*)(sm + off + 4) = h1;
        __nv_bfloat162 l0, l1;
        l0.x = __float2bfloat16_rn(v.x - __bfloat162float(h0.x));
        l0.y = __float2bfloat16_rn(v.y - __bfloat162float(h0.y));
        l1.x = __float2bfloat16_rn(v.z - __bfloat162float(h1.x));
        l1.y = __float2bfloat16_rn(v.w - __bfloat162float(h1.y));
        *(__nv_bfloat162*)(sm + off + 16384)     = l0;
        *(__nv_bfloat162*)(sm + off + 16384 + 4) = l1;
    }
}

// two k16 steps of the 3-pass bf16x3 MMA over a 64x32 warp tile
__device__ __forceinline__ void mma_half(uint32_t Ab, uint32_t Bb, int kk0,
                                         int wm, int wn, int lane,
                                         float (&acc)[4][4][4]) {
    #pragma unroll
    for (int ks = 0; ks < 2; ks++) {
        int kk = kk0 + ks * 16;
        uint32_t ah[4][4], al[4][4], bh[4][2], bl[4][2];
        int lrow = lane & 15;
        int au = (kk >> 3) + (lane >> 4);          // A smem unit
        #pragma unroll
        for (int mi = 0; mi < 4; mi++) {
            int r = wm * 64 + mi * 16 + lrow;
            uint32_t ad = Ab + r * 128 + ((au ^ (r & 7)) << 4);
            ldsm4(ah[mi], ad);
            ldsm4(al[mi], ad + 16384);
        }
        int bu = (kk >> 3) + ((lane >> 3) & 1);    // B smem unit
        #pragma unroll
        for (int bi = 0; bi < 2; bi++) {
            int nr = wn * 32 + bi * 16 + ((lane >> 4) << 3) + (lane & 7);
            uint32_t bd = Bb + nr * 128 + ((bu ^ (nr & 7)) << 4);
            uint32_t t[4];
            ldsm4(t, bd);
            bh[2 * bi][0] = t[0]; bh[2 * bi][1] = t[1];
            bh[2 * bi + 1][0] = t[2]; bh[2 * bi + 1][1] = t[3];
            ldsm4(t, bd + 16384);
            bl[2 * bi][0] = t[0]; bl[2 * bi][1] = t[1];
            bl[2 * bi + 1][0] = t[2]; bl[2 * bi + 1][1] = t[3];
        }
        #pragma unroll
        for (int mi = 0; mi < 4; mi++)
            #pragma unroll
            for (int ni = 0; ni < 4; ni++) {
                mma16816(acc[mi][ni], ah[mi], bh[ni]);
                mma16816(acc[mi][ni], al[mi], bh[ni]);
                mma16816(acc[mi][ni], ah[mi], bl[ni]);
            }
    }
}

// B fp32 register loads (8 float4 per thread), gemm1 variant (gate|up)
__device__ __forceinline__ void ldg_B1(float4* br, const float* __restrict__ gwB,
                                       const float* __restrict__ uwB, int k0, int tid) {
    #pragma unroll
    for (int i = 0; i < 8; i++) {
        int flat = tid + (i << 8);
        int row = flat >> 4, c4 = flat & 15;
        const float* s = (row < 64) ? (gwB + (size_t)row * HDIM)
                                    : (uwB + (size_t)(row - 64) * HDIM);
        br[i] = *(const float4*)(s + k0 + c4 * 4);
    }
}
// gemm2 variant (down_w)
__device__ __forceinline__ void ldg_B2(float4* br, const float* __restrict__ dwB,
                                       int k0, int tid) {
    #pragma unroll
    for (int i = 0; i < 8; i++) {
        int flat = tid + (i << 8);
        int row = flat >> 4, c4 = flat & 15;
        br[i] = *(const float4*)(dwB + (size_t)row * FDIM + k0 + c4 * 4);
    }
}

// ---------------- kernel 3: gate/up GEMM (mbarrier pipeline) + SiLU ----------------
// 256 threads, all dual-role (produce stage c, consume stage c-2)
__global__ void __launch_bounds__(256, 1) gemm1_kernel(const float* __restrict__ gw,
                                                       const float* __restrict__ uw) {
    extern __shared__ char sm[];
    uint32_t sb = smem_u32(sm);
    int e = blockIdx.z;
    int cnt = g_cnt[e];
    int m0 = blockIdx.x << 7;
    if (m0 >= cnt) return;
    int n0f = blockIdx.y << 6;
    int tid = threadIdx.x, lane = tid & 31, wid = tid >> 5;
    int wm = wid & 1, wn = wid >> 1;
    const int NC = HDIM / 64;   // 32

    if (tid == 0) {
        #pragma unroll
        for (int s = 0; s < NST; s++) {
            MBAR_INIT(BAR_FULL(sb, s), 512);   // 256 noinc cp.async arrives + 256 sts arrives
            MBAR_INIT(BAR_EMPTY(sb, s), 8);    // 8 consuming warps
        }
    }
    __syncthreads();

    const __nv_bfloat16* Ahi = g_gah + ((size_t)e * T_TOK + m0) * HDIM;
    const __nv_bfloat16* Alo = g_gal + ((size_t)e * T_TOK + m0) * HDIM;
    const float* gwB = gw + ((size_t)e * FDIM + n0f) * HDIM;
    const float* uwB = uw + ((size_t)e * FDIM + n0f) * HDIM;

    float acc[4][4][4];
    #pragma unroll
    for (int a = 0; a < 4; a++)
        #pragma unroll
        for (int b = 0; b < 4; b++)
            #pragma unroll
            for (int c = 0; c < 4; c++) acc[a][b][c] = 0.f;

    float4 br[8];
    ldg_B1(br, gwB, uwB, 0, tid);

    int ps = 0, pph = 1;   // producer cursor
    int cs = 0, cph = 0;   // consumer cursor
    for (int c = 0; c < NC + 2; c++) {
        if (c < NC) {
            MBAR_WAIT(BAR_EMPTY(sb, ps), pph);
            uint32_t base = sb + ps * STGSZ;
            cpa_tileA(base, Ahi, Alo, HDIM, c << 6, tid);
            MBAR_CPA_ARRIVE(BAR_FULL(sb, ps));
            sts_B<true>(sm, ps * STGSZ + 32768u, br, tid);
            MBAR_ARRIVE(BAR_FULL(sb, ps));
            if (++ps == NST) { ps = 0; pph ^= 1; }
            if (c + 1 < NC) ldg_B1(br, gwB, uwB, (c + 1) << 6, tid);
        }
        if (c >= 2) {
            MBAR_WAIT(BAR_FULL(sb, cs), cph);
            uint32_t Ab = sb + cs * STGSZ;
            uint32_t Bb = Ab + 32768u;
            mma_half(Ab, Bb, 0, wm, wn, lane, acc);
            mma_half(Ab, Bb, 32, wm, wn, lane, acc);
            __syncwarp();
            if (lane == 0) MBAR_ARRIVE(BAR_EMPTY(sb, cs));
            if (++cs == NST) { cs = 0; cph ^= 1; }
        }
    }

    // epilogue: cols 2j/2j+1 = (gate_j, up_j); h = silu(g)*u -> hi/lo bf16
    #pragma unroll
    for (int mi = 0; mi < 4; mi++)
        #pragma unroll
        for (int rh = 0; rh < 2; rh++) {
            int row = wm * 64 + mi * 16 + (lane >> 2) + rh * 8;
            int slot = m0 + row;
            if (slot < cnt) {
                size_t hb = ((size_t)e * T_TOK + slot) * FDIM + n0f;
                #pragma unroll
                for (int ni = 0; ni < 4; ni++) {
                    float g = acc[mi][ni][rh * 2 + 0];
                    float u = acc[mi][ni][rh * 2 + 1];
                    float h = u * g / (1.f + __expf(-g));
                    int j = wn * 16 + ni * 4 + (lane & 3);
                    __nv_bfloat16 hh = __float2bfloat16_rn(h);
                    g_hbh[hb + j] = hh;
                    g_hbl[hb + j] = __float2bfloat16_rn(h - __bfloat162float(hh));
                }
            }
        }
}

// ---------------- kernel 4: down GEMM (mbarrier pipeline) + weighted scatter ----------------
__global__ void __launch_bounds__(256, 1) gemm2_kernel(const float* __restrict__ dw,
                                                       float* __restrict__ out) {
    extern __shared__ char sm[];
    uint32_t sb = smem_u32(sm);
    int e = blockIdx.z;
    int cnt = g_cnt[e];
    int m0 = blockIdx.x << 7;
    if (m0 >= cnt) return;
    int n0 = blockIdx.y << 7;
    int tid = threadIdx.x, lane = tid & 31, wid = tid >> 5;
    int wm = wid & 1, wn = wid >> 1;
    const int NC = FDIM / 64;   // 86

    if (tid == 0) {
        #pragma unroll
        for (int s = 0; s < NST; s++) {
            MBAR_INIT(BAR_FULL(sb, s), 512);
            MBAR_INIT(BAR_EMPTY(sb, s), 8);
        }
    }
    __syncthreads();

    const __nv_bfloat16* Ahi = g_hbh + ((size_t)e * T_TOK + m0) * FDIM;
    const __nv_bfloat16* Alo = g_hbl + ((size_t)e * T_TOK + m0) * FDIM;
    const float* dwB = dw + ((size_t)e * HDIM + n0) * FDIM;

    float acc[4][4][4];
    #pragma unroll
    for (int a = 0; a < 4; a++)
        #pragma unroll
        for (int b = 0; b < 4; b++)
            #pragma unroll
            for (int c = 0; c < 4; c++) acc[a][b][c] = 0.f;

    float4 br[8];
    ldg_B2(br, dwB, 0, tid);

    int ps = 0, pph = 1;
    int cs = 0, cph = 0;
    for (int c = 0; c < NC + 2; c++) {
        if (c < NC) {
            MBAR_WAIT(BAR_EMPTY(sb, ps), pph);
            uint32_t base = sb + ps * STGSZ;
            cpa_tileA(base, Ahi, Alo, FDIM, c << 6, tid);
            MBAR_CPA_ARRIVE(BAR_FULL(sb, ps));
            sts_B<false>(sm, ps * STGSZ + 32768u, br, tid);
            MBAR_ARRIVE(BAR_FULL(sb, ps));
            if (++ps == NST) { ps = 0; pph ^= 1; }
            if (c + 1 < NC) ldg_B2(br, dwB, (c + 1) << 6, tid);
        }
        if (c >= 2) {
            MBAR_WAIT(BAR_FULL(sb, cs), cph);
            uint32_t Ab = sb + cs * STGSZ;
            uint32_t Bb = Ab + 32768u;
            mma_half(Ab, Bb, 0, wm, wn, lane, acc);
            mma_half(Ab, Bb, 32, wm, wn, lane, acc);
            __syncwarp();
            if (lane == 0) MBAR_ARRIVE(BAR_EMPTY(sb, cs));
            if (++cs == NST) { cs = 0; cph ^= 1; }
        }
    }

    // epilogue: weighted atomic scatter to out
    #pragma unroll
    for (int mi = 0; mi < 4; mi++)
        #pragma unroll
        for (int rh = 0; rh < 2; rh++) {
            int row = wm * 64 + mi * 16 + (lane >> 2) + rh * 8;
            int slot = m0 + row;
            if (slot < cnt) {
                int tok = g_ptok[e * T_TOK + slot];
                float w = g_pw[e * T_TOK + slot];
                float* orow = out + (size_t)tok * HDIM + n0;
                #pragma unroll
                for (int ni = 0; ni < 4; ni++) {
                    int col = wn * 32 + ni * 8 + 2 * (lane & 3);
                    atomicAdd(orow + col,     acc[mi][ni][rh * 2 + 0] * w);
                    atomicAdd(orow + col + 1, acc[mi][ni][rh * 2 + 1] * w);
                }
            }
        }
}

// ---------------- launch ----------------
extern "C" void kernel_launch(void* const* d_in, const int* in_sizes, int n_in,
                              void* d_out, int out_size) {
    const float* x  = (const float*)d_in[0];   // [B,S,H]
    const float* rw = (const float*)d_in[1];   // [E,H]
    const float* gw = (const float*)d_in[2];   // [E,F,H]
    const float* uw = (const float*)d_in[3];   // [E,F,H]
    const float* dw = (const float*)d_in[4];   // [E,H,F]
    float* out = (float*)d_out;

    cudaFuncSetAttribute(gemm1_kernel, cudaFuncAttributeMaxDynamicSharedMemorySize, SMEM_GEMM);
    cudaFuncSetAttribute(gemm2_kernel, cudaFuncAttributeMaxDynamicSharedMemorySize, SMEM_GEMM);

    cudaMemsetAsync(out, 0, (size_t)out_size * sizeof(float));
    zero_cnt_kernel<<<1, 32>>>();
    router_kernel<<<T_TOK, 256>>>(x, rw);
    gather_x_kernel<<<EEXP * T_TOK, 128>>>(x);
    gemm1_kernel<<<dim3(16, FDIM / 64, EEXP), 256, SMEM_GEMM>>>(gw, uw);
    gemm2_kernel<<<dim3(16, HDIM / 128, EEXP), 256, SMEM_GEMM>>>(dw, out);
}

// round 8
// speedup vs baseline: 3.2094x; 1.0666x over previous
#include <cuda_runtime.h>
#include <cuda_bf16.h>
#include <cstdint>
#include <math.h>

// ---------------- problem constants ----------------
#define T_TOK 2048
#define HDIM  2048
#define FDIM  5504
#define EEXP  8

// ---------------- device scratch (static, no allocation) ----------------
__device__ int   g_cnt[EEXP];
__device__ int   g_ptok[EEXP * T_TOK];
__device__ float g_pw[EEXP * T_TOK];

#define GAELEM ((size_t)EEXP * (size_t)T_TOK * (size_t)HDIM)
#define HBELEM ((size_t)EEXP * (size_t)T_TOK * (size_t)FDIM)
__device__ __align__(16) __nv_bfloat16 g_gah[GAELEM]; // gathered x hi
__device__ __align__(16) __nv_bfloat16 g_gal[GAELEM]; // gathered x lo
__device__ __align__(16) __nv_bfloat16 g_hbh[HBELEM]; // silu(g)*u hi
__device__ __align__(16) __nv_bfloat16 g_hbl[HBELEM]; // silu(g)*u lo

// ---------------- PTX helpers ----------------
__device__ __forceinline__ uint32_t smem_u32(const void* p) {
    uint32_t a;
    asm("{ .reg .u64 t; cvta.to.shared.u64 t, %1; cvt.u32.u64 %0, t; }"
        : "=r"(a) : "l"(p));
    return a;
}

__device__ __forceinline__ void cpa16(uint32_t dst, const void* src) {
    asm volatile("cp.async.cg.shared.global [%0], [%1], 16;"
                 :: "r"(dst), "l"(src) : "memory");
}

#define MBAR_INIT(addr, cnt) \
    asm volatile("mbarrier.init.shared.b64 [%0], %1;" :: "r"(addr), "r"(cnt) : "memory")
#define MBAR_ARRIVE(addr) \
    asm volatile("mbarrier.arrive.shared.b64 _, [%0];" :: "r"(addr) : "memory")
// arrive (counted against the INIT count: .noinc) on completion of this
// thread's prior cp.async ops
#define MBAR_CPA_ARRIVE(addr) \
    asm volatile("cp.async.mbarrier.arrive.noinc.shared.b64 [%0];" :: "r"(addr) : "memory")
#define MBAR_WAIT(addr, par) do {                                             \
    uint32_t _m = (addr); uint32_t _p = (par); uint32_t _d;                   \
    asm volatile("{\n\t.reg .pred p;\n\t"                                     \
        "mbarrier.try_wait.parity.shared.b64 p, [%1], %2;\n\t"                \
        "selp.b32 %0, 1, 0, p;\n\t}"                                          \
        : "=r"(_d) : "r"(_m), "r"(_p) : "memory");                            \
    if (!_d) {                                                                \
        asm volatile("{\n\t.reg .pred P1;\n\t"                                \
            "WL_%=:\n\t"                                                      \
            "mbarrier.try_wait.parity.shared.b64 P1, [%0], %1;\n\t"           \
            "@P1 bra.uni WD_%=;\n\t"                                          \
            "bra.uni WL_%=;\n\t"                                              \
            "WD_%=:\n\t}"                                                     \
            :: "r"(_m), "r"(_p) : "memory");                                  \
    }                                                                         \
} while (0)

__device__ __forceinline__ void ldsm4(uint32_t* r, uint32_t addr) {
    asm volatile("ldmatrix.sync.aligned.m8n8.x4.shared.b16 {%0,%1,%2,%3}, [%4];"
                 : "=r"(r[0]), "=r"(r[1]), "=r"(r[2]), "=r"(r[3]) : "r"(addr));
}

__device__ __forceinline__ void mma16816(float* c, const uint32_t* a, const uint32_t* b) {
    asm volatile(
        "mma.sync.aligned.m16n8k16.row.col.f32.bf16.bf16.f32 "
        "{%0,%1,%2,%3}, {%4,%5,%6,%7}, {%8,%9}, {%0,%1,%2,%3};"
        : "+f"(c[0]), "+f"(c[1]), "+f"(c[2]), "+f"(c[3])
        : "r"(a[0]), "r"(a[1]), "r"(a[2]), "r"(a[3]), "r"(b[0]), "r"(b[1]));
}

// hi/lo split of 4 floats -> bf16 hi/lo pairs (gmem)
__device__ __forceinline__ void split4(float4 v,
                                       __nv_bfloat16* __restrict__ hi,
                                       __nv_bfloat16* __restrict__ lo,
                                       size_t i) {
    __nv_bfloat162 h0 = __floats2bfloat162_rn(v.x, v.y);
    __nv_bfloat162 h1 = __floats2bfloat162_rn(v.z, v.w);
    *(__nv_bfloat162*)(hi + i)     = h0;
    *(__nv_bfloat162*)(hi + i + 2) = h1;
    __nv_bfloat162 l0, l1;
    l0.x = __float2bfloat16_rn(v.x - __bfloat162float(h0.x));
    l0.y = __float2bfloat16_rn(v.y - __bfloat162float(h0.y));
    l1.x = __float2bfloat16_rn(v.z - __bfloat162float(h1.x));
    l1.y = __float2bfloat16_rn(v.w - __bfloat162float(h1.y));
    *(__nv_bfloat162*)(lo + i)     = l0;
    *(__nv_bfloat162*)(lo + i + 2) = l1;
}

// ---------------- kernel 0: zero counters ----------------
__global__ void zero_cnt_kernel() {
    if (threadIdx.x < EEXP) g_cnt[threadIdx.x] = 0;
}

// ---------------- kernel 1: router ----------------
__global__ void __launch_bounds__(256) router_kernel(const float* __restrict__ x,
                                                     const float* __restrict__ rw) {
    int t = blockIdx.x;
    int warp = threadIdx.x >> 5;
    int lane = threadIdx.x & 31;
    __shared__ float logits[EEXP];

    const float* xr = x + (size_t)t * HDIM;
    const float* wr = rw + (size_t)warp * HDIM;
    float s = 0.f;
    for (int h = lane * 4; h < HDIM; h += 128) {
        float4 xv = *(const float4*)(xr + h);
        float4 wv = *(const float4*)(wr + h);
        s = fmaf(xv.x, wv.x, s);
        s = fmaf(xv.y, wv.y, s);
        s = fmaf(xv.z, wv.z, s);
        s = fmaf(xv.w, wv.w, s);
    }
    #pragma unroll
    for (int o = 16; o; o >>= 1) s += __shfl_down_sync(0xffffffffu, s, o);
    if (lane == 0) logits[warp] = s;
    __syncthreads();

    if (threadIdx.x == 0) {
        int i0 = 0; float v0 = logits[0];
        #pragma unroll
        for (int i = 1; i < EEXP; i++)
            if (logits[i] > v0) { v0 = logits[i]; i0 = i; }
        int i1 = -1; float v1 = -3.0e38f;
        #pragma unroll
        for (int i = 0; i < EEXP; i++) {
            if (i == i0) continue;
            if (logits[i] > v1) { v1 = logits[i]; i1 = i; }
        }
        float e1 = expf(v1 - v0);
        float inv = 1.f / (1.f + e1);
        int s0 = atomicAdd(&g_cnt[i0], 1);
        g_ptok[i0 * T_TOK + s0] = t;
        g_pw  [i0 * T_TOK + s0] = inv;
        int s1 = atomicAdd(&g_cnt[i1], 1);
        g_ptok[i1 * T_TOK + s1] = t;
        g_pw  [i1 * T_TOK + s1] = e1 * inv;
    }
}

// ---------------- kernel 2: gather tokens + bf16 hi/lo split ----------------
__global__ void __launch_bounds__(128) gather_x_kernel(const float* __restrict__ x) {
    int row = blockIdx.x;                 // e*T_TOK + slot
    int e = row >> 11;
    int slot = row & (T_TOK - 1);
    if (slot >= g_cnt[e]) return;
    const float4* src = (const float4*)(x + (size_t)g_ptok[row] * HDIM);
    size_t ob = (size_t)row * HDIM;
    for (int i = threadIdx.x; i < HDIM / 4; i += 128)
        split4(src[i], g_gah, g_gal, ob + (size_t)i * 4);
}

// ---------------- GEMM pipeline layout ----------------
// stage (64KB): A hi 16K @0 | A lo 16K @16384 | B hi 16K @32768 | B lo 16K @49152
// 3 stages; barriers @196608: full[3] (+0,8,16), empty[3] (+24,32,40)
#define STGSZ   65536u
#define NST     3
#define BAR_OFF 196608u
#define SMEM_GEMM 196864
#define BAR_FULL(sb, s)  ((sb) + BAR_OFF + (uint32_t)(s) * 8)
#define BAR_EMPTY(sb, s) ((sb) + BAR_OFF + 24 + (uint32_t)(s) * 8)

// cp.async a 128x64 bf16 hi/lo A tile into SW128-swizzled smem (256 threads)
__device__ __forceinline__ void cpa_tileA(uint32_t base,
                                          const __nv_bfloat16* __restrict__ hi,
                                          const __nv_bfloat16* __restrict__ lo,
                                          size_t stride, int k0, int tid) {
    #pragma unroll
    for (int i = 0; i < 4; i++) {
        int flat = tid + (i << 8);
        int r = flat >> 3, u = flat & 7;
        uint32_t dst = base + r * 128 + ((u ^ (r & 7)) << 4);
        size_t off = (size_t)r * stride + k0 + u * 8;
        cpa16(dst, hi + off);
        cpa16(dst + 16384, lo + off);
    }
}

// store fp32 regs as bf16 hi/lo into swizzled B tile (optionally interleaving
// gate/up rows: smem row = 2*r (gate) / 2*r+1 (up))
template <bool IL>
__device__ __forceinline__ void sts_B(char* sm, uint32_t sboff, const float4* br, int tid) {
    #pragma unroll
    for (int i = 0; i < 8; i++) {
        int flat = tid + (i << 8);
        int row = flat >> 4, c4 = flat & 15;
        int sr = IL ? ((row < 64) ? (row << 1) : (((row - 64) << 1) + 1)) : row;
        uint32_t off = sboff + sr * 128 + (((c4 >> 1) ^ (sr & 7)) << 4) + ((c4 & 1) << 3);
        float4 v = br[i];
        __nv_bfloat162 h0 = __floats2bfloat162_rn(v.x, v.y);
        __nv_bfloat162 h1 = __floats2bfloat162_rn(v.z, v.w);
        *(__nv_bfloat162*)(sm + off)     = h0;
        *(__nv_bfloat162*)(sm + off + 4) = h1;
        __nv_bfloat162 l0, l1;
        l0.x = __float2bfloat16_rn(v.x - __bfloat162float(h0.x));
        l0.y = __float2bfloat16_rn(v.y - __bfloat162float(h0.y));
        l1.x = __float2bfloat16_rn(v.z - __bfloat162float(h1.x));
        l1.y = __float2bfloat16_rn(v.w - __bfloat162float(h1.y));
        *(__nv_bfloat162*)(sm + off + 16384)     = l0;
        *(__nv_bfloat162*)(sm + off + 16384 + 4) = l1;
    }
}

// two k16 steps of the 3-pass bf16x3 MMA over a 64x32 warp tile.
// Pass-outer MMA ordering: 15 independent MMAs between dependent acc reuses.
__device__ __forceinline__ void mma_half(uint32_t Ab, uint32_t Bb, int kk0,
                                         int wm, int wn, int lane,
                                         float (&acc)[4][4][4]) {
    #pragma unroll
    for (int ks = 0; ks < 2; ks++) {
        int kk = kk0 + ks * 16;
        uint32_t ah[4][4], al[4][4], bh[4][2], bl[4][2];
        int lrow = lane & 15;
        int au = (kk >> 3) + (lane >> 4);          // A smem unit
        #pragma unroll
        for (int mi = 0; mi < 4; mi++) {
            int r = wm * 64 + mi * 16 + lrow;
            uint32_t ad = Ab + r * 128 + ((au ^ (r & 7)) << 4);
            ldsm4(ah[mi], ad);
            ldsm4(al[mi], ad + 16384);
        }
        int bu = (kk >> 3) + ((lane >> 3) & 1);    // B smem unit
        #pragma unroll
        for (int bi = 0; bi < 2; bi++) {
            int nr = wn * 32 + bi * 16 + ((lane >> 4) << 3) + (lane & 7);
            uint32_t bd = Bb + nr * 128 + ((bu ^ (nr & 7)) << 4);
            uint32_t t[4];
            ldsm4(t, bd);
            bh[2 * bi][0] = t[0]; bh[2 * bi][1] = t[1];
            bh[2 * bi + 1][0] = t[2]; bh[2 * bi + 1][1] = t[3];
            ldsm4(t, bd + 16384);
            bl[2 * bi][0] = t[0]; bl[2 * bi][1] = t[1];
            bl[2 * bi + 1][0] = t[2]; bl[2 * bi + 1][1] = t[3];
        }
        // pass 0: ah*bh
        #pragma unroll
        for (int mi = 0; mi < 4; mi++)
            #pragma unroll
            for (int ni = 0; ni < 4; ni++)
                mma16816(acc[mi][ni], ah[mi], bh[ni]);
        // pass 1: al*bh
        #pragma unroll
        for (int mi = 0; mi < 4; mi++)
            #pragma unroll
            for (int ni = 0; ni < 4; ni++)
                mma16816(acc[mi][ni], al[mi], bh[ni]);
        // pass 2: ah*bl
        #pragma unroll
        for (int mi = 0; mi < 4; mi++)
            #pragma unroll
            for (int ni = 0; ni < 4; ni++)
                mma16816(acc[mi][ni], ah[mi], bl[ni]);
    }
}

// B fp32 register loads (8 float4 per thread), gemm1 variant (gate|up)
__device__ __forceinline__ void ldg_B1(float4* br, const float* __restrict__ gwB,
                                       const float* __restrict__ uwB, int k0, int tid) {
    #pragma unroll
    for (int i = 0; i < 8; i++) {
        int flat = tid + (i << 8);
        int row = flat >> 4, c4 = flat & 15;
        const float* s = (row < 64) ? (gwB + (size_t)row * HDIM)
                                    : (uwB + (size_t)(row - 64) * HDIM);
        br[i] = *(const float4*)(s + k0 + c4 * 4);
    }
}
// gemm2 variant (down_w)
__device__ __forceinline__ void ldg_B2(float4* br, const float* __restrict__ dwB,
                                       int k0, int tid) {
    #pragma unroll
    for (int i = 0; i < 8; i++) {
        int flat = tid + (i << 8);
        int row = flat >> 4, c4 = flat & 15;
        br[i] = *(const float4*)(dwB + (size_t)row * FDIM + k0 + c4 * 4);
    }
}

// ---------------- kernel 3: gate/up GEMM (mbarrier pipeline) + SiLU ----------------
// 256 threads, all dual-role; producer burst hidden between MMA halves
__global__ void __launch_bounds__(256, 1) gemm1_kernel(const float* __restrict__ gw,
                                                       const float* __restrict__ uw) {
    extern __shared__ char sm[];
    uint32_t sb = smem_u32(sm);
    int e = blockIdx.z;
    int cnt = g_cnt[e];
    int m0 = blockIdx.x << 7;
    if (m0 >= cnt) return;
    int n0f = blockIdx.y << 6;
    int tid = threadIdx.x, lane = tid & 31, wid = tid >> 5;
    int wm = wid & 1, wn = wid >> 1;
    const int NC = HDIM / 64;   // 32

    if (tid == 0) {
        #pragma unroll
        for (int s = 0; s < NST; s++) {
            MBAR_INIT(BAR_FULL(sb, s), 512);   // 256 noinc cp.async arrives + 256 sts arrives
            MBAR_INIT(BAR_EMPTY(sb, s), 8);    // 8 consuming warps
        }
    }
    __syncthreads();

    const __nv_bfloat16* Ahi = g_gah + ((size_t)e * T_TOK + m0) * HDIM;
    const __nv_bfloat16* Alo = g_gal + ((size_t)e * T_TOK + m0) * HDIM;
    const float* gwB = gw + ((size_t)e * FDIM + n0f) * HDIM;
    const float* uwB = uw + ((size_t)e * FDIM + n0f) * HDIM;

    float acc[4][4][4];
    #pragma unroll
    for (int a = 0; a < 4; a++)
        #pragma unroll
        for (int b = 0; b < 4; b++)
            #pragma unroll
            for (int c = 0; c < 4; c++) acc[a][b][c] = 0.f;

    float4 br[8];
    ldg_B1(br, gwB, uwB, 0, tid);

    int ps = 0, pph = 1;   // producer cursor
    int cs = 0, cph = 0;   // consumer cursor
    for (int c = 0; c < NC + 2; c++) {
        uint32_t Ab = sb + cs * STGSZ;
        uint32_t Bb = Ab + 32768u;
        if (c >= 2) {
            MBAR_WAIT(BAR_FULL(sb, cs), cph);
            mma_half(Ab, Bb, 0, wm, wn, lane, acc);
        }
        if (c < NC) {
            MBAR_WAIT(BAR_EMPTY(sb, ps), pph);
            uint32_t base = sb + ps * STGSZ;
            cpa_tileA(base, Ahi, Alo, HDIM, c << 6, tid);
            MBAR_CPA_ARRIVE(BAR_FULL(sb, ps));
            sts_B<true>(sm, ps * STGSZ + 32768u, br, tid);
            MBAR_ARRIVE(BAR_FULL(sb, ps));
            if (++ps == NST) { ps = 0; pph ^= 1; }
            if (c + 1 < NC) ldg_B1(br, gwB, uwB, (c + 1) << 6, tid);
        }
        if (c >= 2) {
            mma_half(Ab, Bb, 32, wm, wn, lane, acc);
            __syncwarp();
            if (lane == 0) MBAR_ARRIVE(BAR_EMPTY(sb, cs));
            if (++cs == NST) { cs = 0; cph ^= 1; }
        }
    }

    // epilogue: cols 2j/2j+1 = (gate_j, up_j); h = silu(g)*u -> hi/lo bf16
    #pragma unroll
    for (int mi = 0; mi < 4; mi++)
        #pragma unroll
        for (int rh = 0; rh < 2; rh++) {
            int row = wm * 64 + mi * 16 + (lane >> 2) + rh * 8;
            int slot = m0 + row;
            if (slot < cnt) {
                size_t hb = ((size_t)e * T_TOK + slot) * FDIM + n0f;
                #pragma unroll
                for (int ni = 0; ni < 4; ni++) {
                    float g = acc[mi][ni][rh * 2 + 0];
                    float u = acc[mi][ni][rh * 2 + 1];
                    float h = u * g / (1.f + __expf(-g));
                    int j = wn * 16 + ni * 4 + (lane & 3);
                    __nv_bfloat16 hh = __float2bfloat16_rn(h);
                    g_hbh[hb + j] = hh;
                    g_hbl[hb + j] = __float2bfloat16_rn(h - __bfloat162float(hh));
                }
            }
        }
}

// ---------------- kernel 4: down GEMM (mbarrier pipeline) + weighted scatter ----------------
__global__ void __launch_bounds__(256, 1) gemm2_kernel(const float* __restrict__ dw,
                                                       float* __restrict__ out) {
    extern __shared__ char sm[];
    uint32_t sb = smem_u32(sm);
    int e = blockIdx.z;
    int cnt = g_cnt[e];
    int m0 = blockIdx.x << 7;
    if (m0 >= cnt) return;
    int n0 = blockIdx.y << 7;
    int tid = threadIdx.x, lane = tid & 31, wid = tid >> 5;
    int wm = wid & 1, wn = wid >> 1;
    const int NC = FDIM / 64;   // 86

    if (tid == 0) {
        #pragma unroll
        for (int s = 0; s < NST; s++) {
            MBAR_INIT(BAR_FULL(sb, s), 512);
            MBAR_INIT(BAR_EMPTY(sb, s), 8);
        }
    }
    __syncthreads();

    const __nv_bfloat16* Ahi = g_hbh + ((size_t)e * T_TOK + m0) * FDIM;
    const __nv_bfloat16* Alo = g_hbl + ((size_t)e * T_TOK + m0) * FDIM;
    const float* dwB = dw + ((size_t)e * HDIM + n0) * FDIM;

    float acc[4][4][4];
    #pragma unroll
    for (int a = 0; a < 4; a++)
        #pragma unroll
        for (int b = 0; b < 4; b++)
            #pragma unroll
            for (int c = 0; c < 4; c++) acc[a][b][c] = 0.f;

    float4 br[8];
    ldg_B2(br, dwB, 0, tid);

    int ps = 0, pph = 1;
    int cs = 0, cph = 0;
    for (int c = 0; c < NC + 2; c++) {
        uint32_t Ab = sb + cs * STGSZ;
        uint32_t Bb = Ab + 32768u;
        if (c >= 2) {
            MBAR_WAIT(BAR_FULL(sb, cs), cph);
            mma_half(Ab, Bb, 0, wm, wn, lane, acc);
        }
        if (c < NC) {
            MBAR_WAIT(BAR_EMPTY(sb, ps), pph);
            uint32_t base = sb + ps * STGSZ;
            cpa_tileA(base, Ahi, Alo, FDIM, c << 6, tid);
            MBAR_CPA_ARRIVE(BAR_FULL(sb, ps));
            sts_B<false>(sm, ps * STGSZ + 32768u, br, tid);
            MBAR_ARRIVE(BAR_FULL(sb, ps));
            if (++ps == NST) { ps = 0; pph ^= 1; }
            if (c + 1 < NC) ldg_B2(br, dwB, (c + 1) << 6, tid);
        }
        if (c >= 2) {
            mma_half(Ab, Bb, 32, wm, wn, lane, acc);
            __syncwarp();
            if (lane == 0) MBAR_ARRIVE(BAR_EMPTY(sb, cs));
            if (++cs == NST) { cs = 0; cph ^= 1; }
        }
    }

    // epilogue: weighted atomic scatter to out
    #pragma unroll
    for (int mi = 0; mi < 4; mi++)
        #pragma unroll
        for (int rh = 0; rh < 2; rh++) {
            int row = wm * 64 + mi * 16 + (lane >> 2) + rh * 8;
            int slot = m0 + row;
            if (slot < cnt) {
                int tok = g_ptok[e * T_TOK + slot];
                float w = g_pw[e * T_TOK + slot];
                float* orow = out + (size_t)tok * HDIM + n0;
                #pragma unroll
                for (int ni = 0; ni < 4; ni++) {
                    int col = wn * 32 + ni * 8 + 2 * (lane & 3);
                    atomicAdd(orow + col,     acc[mi][ni][rh * 2 + 0] * w);
                    atomicAdd(orow + col + 1, acc[mi][ni][rh * 2 + 1] * w);
                }
            }
        }
}

// ---------------- launch ----------------
extern "C" void kernel_launch(void* const* d_in, const int* in_sizes, int n_in,
                              void* d_out, int out_size) {
    const float* x  = (const float*)d_in[0];   // [B,S,H]
    const float* rw = (const float*)d_in[1];   // [E,H]
    const float* gw = (const float*)d_in[2];   // [E,F,H]
    const float* uw = (const float*)d_in[3];   // [E,F,H]
    const float* dw = (const float*)d_in[4];   // [E,H,F]
    float* out = (float*)d_out;

    cudaFuncSetAttribute(gemm1_kernel, cudaFuncAttributeMaxDynamicSharedMemorySize, SMEM_GEMM);
    cudaFuncSetAttribute(gemm2_kernel, cudaFuncAttributeMaxDynamicSharedMemorySize, SMEM_GEMM);

    cudaMemsetAsync(out, 0, (size_t)out_size * sizeof(float));
    zero_cnt_kernel<<<1, 32>>>();
    router_kernel<<<T_TOK, 256>>>(x, rw);
    gather_x_kernel<<<EEXP * T_TOK, 128>>>(x);
    gemm1_kernel<<<dim3(16, FDIM / 64, EEXP), 256, SMEM_GEMM>>>(gw, uw);
    gemm2_kernel<<<dim3(16, HDIM / 128, EEXP), 256, SMEM_GEMM>>>(dw, out);
}

// round 9
// speedup vs baseline: 4.6190x; 1.4392x over previous
#include <cuda_runtime.h>
#include <cuda_fp16.h>
#include <cstdint>
#include <math.h>

// ---------------- problem constants ----------------
#define T_TOK 2048
#define HDIM  2048
#define FDIM  5504
#define EEXP  8

// ---------------- device scratch (static, no allocation) ----------------
__device__ int   g_cnt[EEXP];
__device__ int   g_ptok[EEXP * T_TOK];
__device__ float g_pw[EEXP * T_TOK];

#define GAELEM ((size_t)EEXP * (size_t)T_TOK * (size_t)HDIM)
#define HBELEM ((size_t)EEXP * (size_t)T_TOK * (size_t)FDIM)
__device__ __align__(16) __half g_gah[GAELEM]; // gathered x hi
__device__ __align__(16) __half g_gal[GAELEM]; // gathered x lo
__device__ __align__(16) __half g_hbh[HBELEM]; // silu(g)*u hi
__device__ __align__(16) __half g_hbl[HBELEM]; // silu(g)*u lo

// ---------------- PTX helpers ----------------
__device__ __forceinline__ uint32_t smem_u32(const void* p) {
    uint32_t a;
    asm("{ .reg .u64 t; cvta.to.shared.u64 t, %1; cvt.u32.u64 %0, t; }"
        : "=r"(a) : "l"(p));
    return a;
}

__device__ __forceinline__ void cpa16(uint32_t dst, const void* src) {
    asm volatile("cp.async.cg.shared.global [%0], [%1], 16;"
                 :: "r"(dst), "l"(src) : "memory");
}

#define MBAR_INIT(addr, cnt) \
    asm volatile("mbarrier.init.shared.b64 [%0], %1;" :: "r"(addr), "r"(cnt) : "memory")
#define MBAR_ARRIVE(addr) \
    asm volatile("mbarrier.arrive.shared.b64 _, [%0];" :: "r"(addr) : "memory")
// arrive (counted against the INIT count: .noinc) on completion of this
// thread's prior cp.async ops
#define MBAR_CPA_ARRIVE(addr) \
    asm volatile("cp.async.mbarrier.arrive.noinc.shared.b64 [%0];" :: "r"(addr) : "memory")
#define MBAR_WAIT(addr, par) do {                                             \
    uint32_t _m = (addr); uint32_t _p = (par); uint32_t _d;                   \
    asm volatile("{\n\t.reg .pred p;\n\t"                                     \
        "mbarrier.try_wait.parity.shared.b64 p, [%1], %2;\n\t"                \
        "selp.b32 %0, 1, 0, p;\n\t}"                                          \
        : "=r"(_d) : "r"(_m), "r"(_p) : "memory");                            \
    if (!_d) {                                                                \
        asm volatile("{\n\t.reg .pred P1;\n\t"                                \
            "WL_%=:\n\t"                                                      \
            "mbarrier.try_wait.parity.shared.b64 P1, [%0], %1;\n\t"           \
            "@P1 bra.uni WD_%=;\n\t"                                          \
            "bra.uni WL_%=;\n\t"                                              \
            "WD_%=:\n\t}"                                                     \
            :: "r"(_m), "r"(_p) : "memory");                                  \
    }                                                                         \
} while (0)

__device__ __forceinline__ void ldsm4(uint32_t* r, uint32_t addr) {
    asm volatile("ldmatrix.sync.aligned.m8n8.x4.shared.b16 {%0,%1,%2,%3}, [%4];"
                 : "=r"(r[0]), "=r"(r[1]), "=r"(r[2]), "=r"(r[3]) : "r"(addr));
}

__device__ __forceinline__ void mma16816(float* c, const uint32_t* a, const uint32_t* b) {
    asm volatile(
        "mma.sync.aligned.m16n8k16.row.col.f32.f16.f16.f32 "
        "{%0,%1,%2,%3}, {%4,%5,%6,%7}, {%8,%9}, {%0,%1,%2,%3};"
        : "+f"(c[0]), "+f"(c[1]), "+f"(c[2]), "+f"(c[3])
        : "r"(a[0]), "r"(a[1]), "r"(a[2]), "r"(a[3]), "r"(b[0]), "r"(b[1]));
}

// hi/lo split of 4 floats -> fp16 hi/lo pairs (gmem)
__device__ __forceinline__ void split4(float4 v,
                                       __half* __restrict__ hi,
                                       __half* __restrict__ lo,
                                       size_t i) {
    __half2 h0 = __floats2half2_rn(v.x, v.y);
    __half2 h1 = __floats2half2_rn(v.z, v.w);
    *(__half2*)(hi + i)     = h0;
    *(__half2*)(hi + i + 2) = h1;
    __half2 l0 = __floats2half2_rn(v.x - __low2float(h0), v.y - __high2float(h0));
    __half2 l1 = __floats2half2_rn(v.z - __low2float(h1), v.w - __high2float(h1));
    *(__half2*)(lo + i)     = l0;
    *(__half2*)(lo + i + 2) = l1;
}

// ---------------- kernel 0: zero counters ----------------
__global__ void zero_cnt_kernel() {
    if (threadIdx.x < EEXP) g_cnt[threadIdx.x] = 0;
}

// ---------------- kernel 1: router ----------------
__global__ void __launch_bounds__(256) router_kernel(const float* __restrict__ x,
                                                     const float* __restrict__ rw) {
    int t = blockIdx.x;
    int warp = threadIdx.x >> 5;
    int lane = threadIdx.x & 31;
    __shared__ float logits[EEXP];

    const float* xr = x + (size_t)t * HDIM;
    const float* wr = rw + (size_t)warp * HDIM;
    float s = 0.f;
    for (int h = lane * 4; h < HDIM; h += 128) {
        float4 xv = *(const float4*)(xr + h);
        float4 wv = *(const float4*)(wr + h);
        s = fmaf(xv.x, wv.x, s);
        s = fmaf(xv.y, wv.y, s);
        s = fmaf(xv.z, wv.z, s);
        s = fmaf(xv.w, wv.w, s);
    }
    #pragma unroll
    for (int o = 16; o; o >>= 1) s += __shfl_down_sync(0xffffffffu, s, o);
    if (lane == 0) logits[warp] = s;
    __syncthreads();

    if (threadIdx.x == 0) {
        int i0 = 0; float v0 = logits[0];
        #pragma unroll
        for (int i = 1; i < EEXP; i++)
            if (logits[i] > v0) { v0 = logits[i]; i0 = i; }
        int i1 = -1; float v1 = -3.0e38f;
        #pragma unroll
        for (int i = 0; i < EEXP; i++) {
            if (i == i0) continue;
            if (logits[i] > v1) { v1 = logits[i]; i1 = i; }
        }
        float e1 = expf(v1 - v0);
        float inv = 1.f / (1.f + e1);
        int s0 = atomicAdd(&g_cnt[i0], 1);
        g_ptok[i0 * T_TOK + s0] = t;
        g_pw  [i0 * T_TOK + s0] = inv;
        int s1 = atomicAdd(&g_cnt[i1], 1);
        g_ptok[i1 * T_TOK + s1] = t;
        g_pw  [i1 * T_TOK + s1] = e1 * inv;
    }
}

// ---------------- kernel 2: gather tokens + fp16 hi/lo split ----------------
__global__ void __launch_bounds__(128) gather_x_kernel(const float* __restrict__ x) {
    int row = blockIdx.x;                 // e*T_TOK + slot
    int e = row >> 11;
    int slot = row & (T_TOK - 1);
    if (slot >= g_cnt[e]) return;
    const float4* src = (const float4*)(x + (size_t)g_ptok[row] * HDIM);
    size_t ob = (size_t)row * HDIM;
    for (int i = threadIdx.x; i < HDIM / 4; i += 128)
        split4(src[i], g_gah, g_gal, ob + (size_t)i * 4);
}

// ---------------- GEMM pipeline layout ----------------
// stage (48KB): A hi 16K @0 | A lo 16K @16384 | B fp16 16K @32768
// 4 stages = 196608; barriers @196608: full[4] (+0..24), empty[4] (+32..56)
#define STGSZ   49152u
#define NST     4
#define BAR_OFF 196608u
#define SMEM_GEMM 196864
#define BAR_FULL(sb, s)  ((sb) + BAR_OFF + (uint32_t)(s) * 8)
#define BAR_EMPTY(sb, s) ((sb) + BAR_OFF + 32 + (uint32_t)(s) * 8)

// cp.async a 128x64 fp16 hi/lo A tile into SW128-swizzled smem (256 threads)
__device__ __forceinline__ void cpa_tileA(uint32_t base,
                                          const __half* __restrict__ hi,
                                          const __half* __restrict__ lo,
                                          size_t stride, int k0, int tid) {
    #pragma unroll
    for (int i = 0; i < 4; i++) {
        int flat = tid + (i << 8);
        int r = flat >> 3, u = flat & 7;
        uint32_t dst = base + r * 128 + ((u ^ (r & 7)) << 4);
        size_t off = (size_t)r * stride + k0 + u * 8;
        cpa16(dst, hi + off);
        cpa16(dst + 16384, lo + off);
    }
}

// store fp32 regs as single-rounded fp16 into swizzled B tile (optionally
// interleaving gate/up rows: smem row = 2*r (gate) / 2*r+1 (up))
template <bool IL>
__device__ __forceinline__ void sts_B(char* sm, uint32_t sboff, const float4* br, int tid) {
    #pragma unroll
    for (int i = 0; i < 8; i++) {
        int flat = tid + (i << 8);
        int row = flat >> 4, c4 = flat & 15;
        int sr = IL ? ((row < 64) ? (row << 1) : (((row - 64) << 1) + 1)) : row;
        uint32_t off = sboff + sr * 128 + (((c4 >> 1) ^ (sr & 7)) << 4) + ((c4 & 1) << 3);
        float4 v = br[i];
        __half2 h0 = __floats2half2_rn(v.x, v.y);
        __half2 h1 = __floats2half2_rn(v.z, v.w);
        uint2 hp = make_uint2(*(uint32_t*)&h0, *(uint32_t*)&h1);
        *(uint2*)(sm + off) = hp;
    }
}

// two k16 steps of the 2-pass fp16 MMA over a 64x32 warp tile.
// Pass-outer ordering: 15 independent MMAs between dependent acc reuses.
__device__ __forceinline__ void mma_half(uint32_t Ab, uint32_t Bb, int kk0,
                                         int wm, int wn, int lane,
                                         float (&acc)[4][4][4]) {
    #pragma unroll
    for (int ks = 0; ks < 2; ks++) {
        int kk = kk0 + ks * 16;
        uint32_t ah[4][4], al[4][4], bh[4][2];
        int lrow = lane & 15;
        int au = (kk >> 3) + (lane >> 4);          // A smem unit
        #pragma unroll
        for (int mi = 0; mi < 4; mi++) {
            int r = wm * 64 + mi * 16 + lrow;
            uint32_t ad = Ab + r * 128 + ((au ^ (r & 7)) << 4);
            ldsm4(ah[mi], ad);
            ldsm4(al[mi], ad + 16384);
        }
        int bu = (kk >> 3) + ((lane >> 3) & 1);    // B smem unit
        #pragma unroll
        for (int bi = 0; bi < 2; bi++) {
            int nr = wn * 32 + bi * 16 + ((lane >> 4) << 3) + (lane & 7);
            uint32_t bd = Bb + nr * 128 + ((bu ^ (nr & 7)) << 4);
            uint32_t t[4];
            ldsm4(t, bd);
            bh[2 * bi][0] = t[0]; bh[2 * bi][1] = t[1];
            bh[2 * bi + 1][0] = t[2]; bh[2 * bi + 1][1] = t[3];
        }
        // pass 0: ah*bh
        #pragma unroll
        for (int mi = 0; mi < 4; mi++)
            #pragma unroll
            for (int ni = 0; ni < 4; ni++)
                mma16816(acc[mi][ni], ah[mi], bh[ni]);
        // pass 1: al*bh
        #pragma unroll
        for (int mi = 0; mi < 4; mi++)
            #pragma unroll
            for (int ni = 0; ni < 4; ni++)
                mma16816(acc[mi][ni], al[mi], bh[ni]);
    }
}

// B fp32 register loads (8 float4 per thread), gemm1 variant (gate|up)
__device__ __forceinline__ void ldg_B1(float4* br, const float* __restrict__ gwB,
                                       const float* __restrict__ uwB, int k0, int tid) {
    #pragma unroll
    for (int i = 0; i < 8; i++) {
        int flat = tid + (i << 8);
        int row = flat >> 4, c4 = flat & 15;
        const float* s = (row < 64) ? (gwB + (size_t)row * HDIM)
                                    : (uwB + (size_t)(row - 64) * HDIM);
        br[i] = *(const float4*)(s + k0 + c4 * 4);
    }
}
// gemm2 variant (down_w)
__device__ __forceinline__ void ldg_B2(float4* br, const float* __restrict__ dwB,
                                       int k0, int tid) {
    #pragma unroll
    for (int i = 0; i < 8; i++) {
        int flat = tid + (i << 8);
        int row = flat >> 4, c4 = flat & 15;
        br[i] = *(const float4*)(dwB + (size_t)row * FDIM + k0 + c4 * 4);
    }
}

// ---------------- kernel 3: gate/up GEMM (mbarrier pipeline) + SiLU ----------------
// 256 threads, all dual-role; producer burst hidden between MMA halves
__global__ void __launch_bounds__(256, 1) gemm1_kernel(const float* __restrict__ gw,
                                                       const float* __restrict__ uw) {
    extern __shared__ char sm[];
    uint32_t sb = smem_u32(sm);
    int e = blockIdx.z;
    int cnt = g_cnt[e];
    int m0 = blockIdx.x << 7;
    if (m0 >= cnt) return;
    int n0f = blockIdx.y << 6;
    int tid = threadIdx.x, lane = tid & 31, wid = tid >> 5;
    int wm = wid & 1, wn = wid >> 1;
    const int NC = HDIM / 64;   // 32

    if (tid == 0) {
        #pragma unroll
        for (int s = 0; s < NST; s++) {
            MBAR_INIT(BAR_FULL(sb, s), 512);   // 256 noinc cp.async arrives + 256 sts arrives
            MBAR_INIT(BAR_EMPTY(sb, s), 8);    // 8 consuming warps
        }
    }
    __syncthreads();

    const __half* Ahi = g_gah + ((size_t)e * T_TOK + m0) * HDIM;
    const __half* Alo = g_gal + ((size_t)e * T_TOK + m0) * HDIM;
    const float* gwB = gw + ((size_t)e * FDIM + n0f) * HDIM;
    const float* uwB = uw + ((size_t)e * FDIM + n0f) * HDIM;

    float acc[4][4][4];
    #pragma unroll
    for (int a = 0; a < 4; a++)
        #pragma unroll
        for (int b = 0; b < 4; b++)
            #pragma unroll
            for (int c = 0; c < 4; c++) acc[a][b][c] = 0.f;

    float4 br[8];
    ldg_B1(br, gwB, uwB, 0, tid);

    int ps = 0, pph = 1;   // producer cursor
    int cs = 0, cph = 0;   // consumer cursor
    for (int c = 0; c < NC + 2; c++) {
        uint32_t Ab = sb + cs * STGSZ;
        uint32_t Bb = Ab + 32768u;
        if (c >= 2) {
            MBAR_WAIT(BAR_FULL(sb, cs), cph);
            mma_half(Ab, Bb, 0, wm, wn, lane, acc);
        }
        if (c < NC) {
            MBAR_WAIT(BAR_EMPTY(sb, ps), pph);
            uint32_t base = sb + ps * STGSZ;
            cpa_tileA(base, Ahi, Alo, HDIM, c << 6, tid);
            MBAR_CPA_ARRIVE(BAR_FULL(sb, ps));
            sts_B<true>(sm, ps * STGSZ + 32768u, br, tid);
            MBAR_ARRIVE(BAR_FULL(sb, ps));
            if (++ps == NST) { ps = 0; pph ^= 1; }
            if (c + 1 < NC) ldg_B1(br, gwB, uwB, (c + 1) << 6, tid);
        }
        if (c >= 2) {
            mma_half(Ab, Bb, 32, wm, wn, lane, acc);
            __syncwarp();
            if (lane == 0) MBAR_ARRIVE(BAR_EMPTY(sb, cs));
            if (++cs == NST) { cs = 0; cph ^= 1; }
        }
    }

    // epilogue: cols 2j/2j+1 = (gate_j, up_j); h = silu(g)*u -> hi/lo fp16
    #pragma unroll
    for (int mi = 0; mi < 4; mi++)
        #pragma unroll
        for (int rh = 0; rh < 2; rh++) {
            int row = wm * 64 + mi * 16 + (lane >> 2) + rh * 8;
            int slot = m0 + row;
            if (slot < cnt) {
                size_t hb = ((size_t)e * T_TOK + slot) * FDIM + n0f;
                #pragma unroll
                for (int ni = 0; ni < 4; ni++) {
                    float g = acc[mi][ni][rh * 2 + 0];
                    float u = acc[mi][ni][rh * 2 + 1];
                    float h = u * g / (1.f + __expf(-g));
                    int j = wn * 16 + ni * 4 + (lane & 3);
                    __half hh = __float2half_rn(h);
                    g_hbh[hb + j] = hh;
                    g_hbl[hb + j] = __float2half_rn(h - __half2float(hh));
                }
            }
        }
}

// ---------------- kernel 4: down GEMM (mbarrier pipeline) + weighted scatter ----------------
__global__ void __launch_bounds__(256, 1) gemm2_kernel(const float* __restrict__ dw,
                                                       float* __restrict__ out) {
    extern __shared__ char sm[];
    uint32_t sb = smem_u32(sm);
    int e = blockIdx.z;
    int cnt = g_cnt[e];
    int m0 = blockIdx.x << 7;
    if (m0 >= cnt) return;
    int n0 = blockIdx.y << 7;
    int tid = threadIdx.x, lane = tid & 31, wid = tid >> 5;
    int wm = wid & 1, wn = wid >> 1;
    const int NC = FDIM / 64;   // 86

    if (tid == 0) {
        #pragma unroll
        for (int s = 0; s < NST; s++) {
            MBAR_INIT(BAR_FULL(sb, s), 512);
            MBAR_INIT(BAR_EMPTY(sb, s), 8);
        }
    }
    __syncthreads();

    const __half* Ahi = g_hbh + ((size_t)e * T_TOK + m0) * FDIM;
    const __half* Alo = g_hbl + ((size_t)e * T_TOK + m0) * FDIM;
    const float* dwB = dw + ((size_t)e * HDIM + n0) * FDIM;

    float acc[4][4][4];
    #pragma unroll
    for (int a = 0; a < 4; a++)
        #pragma unroll
        for (int b = 0; b < 4; b++)
            #pragma unroll
            for (int c = 0; c < 4; c++) acc[a][b][c] = 0.f;

    float4 br[8];
    ldg_B2(br, dwB, 0, tid);

    int ps = 0, pph = 1;
    int cs = 0, cph = 0;
    for (int c = 0; c < NC + 2; c++) {
        uint32_t Ab = sb + cs * STGSZ;
        uint32_t Bb = Ab + 32768u;
        if (c >= 2) {
            MBAR_WAIT(BAR_FULL(sb, cs), cph);
            mma_half(Ab, Bb, 0, wm, wn, lane, acc);
        }
        if (c < NC) {
            MBAR_WAIT(BAR_EMPTY(sb, ps), pph);
            uint32_t base = sb + ps * STGSZ;
            cpa_tileA(base, Ahi, Alo, FDIM, c << 6, tid);
            MBAR_CPA_ARRIVE(BAR_FULL(sb, ps));
            sts_B<false>(sm, ps * STGSZ + 32768u, br, tid);
            MBAR_ARRIVE(BAR_FULL(sb, ps));
            if (++ps == NST) { ps = 0; pph ^= 1; }
            if (c + 1 < NC) ldg_B2(br, dwB, (c + 1) << 6, tid);
        }
        if (c >= 2) {
            mma_half(Ab, Bb, 32, wm, wn, lane, acc);
            __syncwarp();
            if (lane == 0) MBAR_ARRIVE(BAR_EMPTY(sb, cs));
            if (++cs == NST) { cs = 0; cph ^= 1; }
        }
    }

    // epilogue: weighted atomic scatter to out
    #pragma unroll
    for (int mi = 0; mi < 4; mi++)
        #pragma unroll
        for (int rh = 0; rh < 2; rh++) {
            int row = wm * 64 + mi * 16 + (lane >> 2) + rh * 8;
            int slot = m0 + row;
            if (slot < cnt) {
                int tok = g_ptok[e * T_TOK + slot];
                float w = g_pw[e * T_TOK + slot];
                float* orow = out + (size_t)tok * HDIM + n0;
                #pragma unroll
                for (int ni = 0; ni < 4; ni++) {
                    int col = wn * 32 + ni * 8 + 2 * (lane & 3);
                    atomicAdd(orow + col,     acc[mi][ni][rh * 2 + 0] * w);
                    atomicAdd(orow + col + 1, acc[mi][ni][rh * 2 + 1] * w);
                }
            }
        }
}

// ---------------- launch ----------------
extern "C" void kernel_launch(void* const* d_in, const int* in_sizes, int n_in,
                              void* d_out, int out_size) {
    const float* x  = (const float*)d_in[0];   // [B,S,H]
    const float* rw = (const float*)d_in[1];   // [E,H]
    const float* gw = (const float*)d_in[2];   // [E,F,H]
    const float* uw = (const float*)d_in[3];   // [E,F,H]
    const float* dw = (const float*)d_in[4];   // [E,H,F]
    float* out = (float*)d_out;

    cudaFuncSetAttribute(gemm1_kernel, cudaFuncAttributeMaxDynamicSharedMemorySize, SMEM_GEMM);
    cudaFuncSetAttribute(gemm2_kernel, cudaFuncAttributeMaxDynamicSharedMemorySize, SMEM_GEMM);

    cudaMemsetAsync(out, 0, (size_t)out_size * sizeof(float));
    zero_cnt_kernel<<<1, 32>>>();
    router_kernel<<<T_TOK, 256>>>(x, rw);
    gather_x_kernel<<<EEXP * T_TOK, 128>>>(x);
    gemm1_kernel<<<dim3(16, FDIM / 64, EEXP), 256, SMEM_GEMM>>>(gw, uw);
    gemm2_kernel<<<dim3(16, HDIM / 128, EEXP), 256, SMEM_GEMM>>>(dw, out);
}

// round 10
// speedup vs baseline: 7.1189x; 1.5412x over previous
#include <cuda_runtime.h>
#include <cuda_fp16.h>
#include <cstdint>
#include <math.h>

// ---------------- problem constants ----------------
#define T_TOK 2048
#define HDIM  2048
#define FDIM  5504
#define EEXP  8

// ---------------- device scratch (static, no allocation) ----------------
__device__ int   g_cnt[EEXP];
__device__ int   g_ptok[EEXP * T_TOK];
__device__ float g_pw[EEXP * T_TOK];

#define GAELEM ((size_t)EEXP * (size_t)T_TOK * (size_t)HDIM)
#define HBELEM ((size_t)EEXP * (size_t)T_TOK * (size_t)FDIM)
__device__ __align__(16) __half g_gah[GAELEM]; // gathered x (fp16)
__device__ __align__(16) __half g_hbh[HBELEM]; // silu(g)*u (fp16)

// ---------------- PTX helpers ----------------
__device__ __forceinline__ uint32_t smem_u32(const void* p) {
    uint32_t a;
    asm("{ .reg .u64 t; cvta.to.shared.u64 t, %1; cvt.u32.u64 %0, t; }"
        : "=r"(a) : "l"(p));
    return a;
}

__device__ __forceinline__ void cpa16(uint32_t dst, const void* src) {
    asm volatile("cp.async.cg.shared.global [%0], [%1], 16;"
                 :: "r"(dst), "l"(src) : "memory");
}

#define MBAR_INIT(addr, cnt) \
    asm volatile("mbarrier.init.shared.b64 [%0], %1;" :: "r"(addr), "r"(cnt) : "memory")
#define MBAR_ARRIVE(addr) \
    asm volatile("mbarrier.arrive.shared.b64 _, [%0];" :: "r"(addr) : "memory")
// arrive (counted against the INIT count: .noinc) on completion of this
// thread's prior cp.async ops
#define MBAR_CPA_ARRIVE(addr) \
    asm volatile("cp.async.mbarrier.arrive.noinc.shared.b64 [%0];" :: "r"(addr) : "memory")
#define MBAR_WAIT(addr, par) do {                                             \
    uint32_t _m = (addr); uint32_t _p = (par); uint32_t _d;                   \
    asm volatile("{\n\t.reg .pred p;\n\t"                                     \
        "mbarrier.try_wait.parity.shared.b64 p, [%1], %2;\n\t"                \
        "selp.b32 %0, 1, 0, p;\n\t}"                                          \
        : "=r"(_d) : "r"(_m), "r"(_p) : "memory");                            \
    if (!_d) {                                                                \
        asm volatile("{\n\t.reg .pred P1;\n\t"                                \
            "WL_%=:\n\t"                                                      \
            "mbarrier.try_wait.parity.shared.b64 P1, [%0], %1;\n\t"           \
            "@P1 bra.uni WD_%=;\n\t"                                          \
            "bra.uni WL_%=;\n\t"                                              \
            "WD_%=:\n\t}"                                                     \
            :: "r"(_m), "r"(_p) : "memory");                                  \
    }                                                                         \
} while (0)

__device__ __forceinline__ void ldsm4(uint32_t* r, uint32_t addr) {
    asm volatile("ldmatrix.sync.aligned.m8n8.x4.shared.b16 {%0,%1,%2,%3}, [%4];"
                 : "=r"(r[0]), "=r"(r[1]), "=r"(r[2]), "=r"(r[3]) : "r"(addr));
}

__device__ __forceinline__ void mma16816(float* c, const uint32_t* a, const uint32_t* b) {
    asm volatile(
        "mma.sync.aligned.m16n8k16.row.col.f32.f16.f16.f32 "
        "{%0,%1,%2,%3}, {%4,%5,%6,%7}, {%8,%9}, {%0,%1,%2,%3};"
        : "+f"(c[0]), "+f"(c[1]), "+f"(c[2]), "+f"(c[3])
        : "r"(a[0]), "r"(a[1]), "r"(a[2]), "r"(a[3]), "r"(b[0]), "r"(b[1]));
}

// ---------------- kernel 0: zero counters ----------------
__global__ void zero_cnt_kernel() {
    if (threadIdx.x < EEXP) g_cnt[threadIdx.x] = 0;
}

// ---------------- kernel 1: router (fp32, exact top-k) ----------------
__global__ void __launch_bounds__(256) router_kernel(const float* __restrict__ x,
                                                     const float* __restrict__ rw) {
    int t = blockIdx.x;
    int warp = threadIdx.x >> 5;
    int lane = threadIdx.x & 31;
    __shared__ float logits[EEXP];

    const float* xr = x + (size_t)t * HDIM;
    const float* wr = rw + (size_t)warp * HDIM;
    float s = 0.f;
    for (int h = lane * 4; h < HDIM; h += 128) {
        float4 xv = *(const float4*)(xr + h);
        float4 wv = *(const float4*)(wr + h);
        s = fmaf(xv.x, wv.x, s);
        s = fmaf(xv.y, wv.y, s);
        s = fmaf(xv.z, wv.z, s);
        s = fmaf(xv.w, wv.w, s);
    }
    #pragma unroll
    for (int o = 16; o; o >>= 1) s += __shfl_down_sync(0xffffffffu, s, o);
    if (lane == 0) logits[warp] = s;
    __syncthreads();

    if (threadIdx.x == 0) {
        int i0 = 0; float v0 = logits[0];
        #pragma unroll
        for (int i = 1; i < EEXP; i++)
            if (logits[i] > v0) { v0 = logits[i]; i0 = i; }
        int i1 = -1; float v1 = -3.0e38f;
        #pragma unroll
        for (int i = 0; i < EEXP; i++) {
            if (i == i0) continue;
            if (logits[i] > v1) { v1 = logits[i]; i1 = i; }
        }
        float e1 = expf(v1 - v0);
        float inv = 1.f / (1.f + e1);
        int s0 = atomicAdd(&g_cnt[i0], 1);
        g_ptok[i0 * T_TOK + s0] = t;
        g_pw  [i0 * T_TOK + s0] = inv;
        int s1 = atomicAdd(&g_cnt[i1], 1);
        g_ptok[i1 * T_TOK + s1] = t;
        g_pw  [i1 * T_TOK + s1] = e1 * inv;
    }
}

// ---------------- kernel 2: gather tokens -> fp16 ----------------
__global__ void __launch_bounds__(128) gather_x_kernel(const float* __restrict__ x) {
    int row = blockIdx.x;                 // e*T_TOK + slot
    int e = row >> 11;
    int slot = row & (T_TOK - 1);
    if (slot >= g_cnt[e]) return;
    const float4* src = (const float4*)(x + (size_t)g_ptok[row] * HDIM);
    size_t ob = (size_t)row * HDIM;
    for (int i = threadIdx.x; i < HDIM / 4; i += 128) {
        float4 v = src[i];
        __half2 h0 = __floats2half2_rn(v.x, v.y);
        __half2 h1 = __floats2half2_rn(v.z, v.w);
        *(__half2*)(g_gah + ob + i * 4)     = h0;
        *(__half2*)(g_gah + ob + i * 4 + 2) = h1;
    }
}

// ---------------- GEMM pipeline layout ----------------
// stage (32KB): A fp16 16K @0 | B fp16 16K @16384
// 4 stages = 131072; barriers @131072: full[4] (+0..24), empty[4] (+32..56)
#define STGSZ   32768u
#define NST     4
#define BAR_OFF 131072u
#define SMEM_GEMM 131328
#define BAR_FULL(sb, s)  ((sb) + BAR_OFF + (uint32_t)(s) * 8)
#define BAR_EMPTY(sb, s) ((sb) + BAR_OFF + 32 + (uint32_t)(s) * 8)

// cp.async a 128x64 fp16 A tile into SW128-swizzled smem (256 threads)
__device__ __forceinline__ void cpa_tileA(uint32_t base,
                                          const __half* __restrict__ A,
                                          size_t stride, int k0, int tid) {
    #pragma unroll
    for (int i = 0; i < 4; i++) {
        int flat = tid + (i << 8);
        int r = flat >> 3, u = flat & 7;
        uint32_t dst = base + r * 128 + ((u ^ (r & 7)) << 4);
        size_t off = (size_t)r * stride + k0 + u * 8;
        cpa16(dst, A + off);
    }
}

// store fp32 regs as single-rounded fp16 into swizzled B tile (optionally
// interleaving gate/up rows: smem row = 2*r (gate) / 2*r+1 (up))
template <bool IL>
__device__ __forceinline__ void sts_B(char* sm, uint32_t sboff, const float4* br, int tid) {
    #pragma unroll
    for (int i = 0; i < 8; i++) {
        int flat = tid + (i << 8);
        int row = flat >> 4, c4 = flat & 15;
        int sr = IL ? ((row < 64) ? (row << 1) : (((row - 64) << 1) + 1)) : row;
        uint32_t off = sboff + sr * 128 + (((c4 >> 1) ^ (sr & 7)) << 4) + ((c4 & 1) << 3);
        float4 v = br[i];
        __half2 h0 = __floats2half2_rn(v.x, v.y);
        __half2 h1 = __floats2half2_rn(v.z, v.w);
        uint2 hp = make_uint2(*(uint32_t*)&h0, *(uint32_t*)&h1);
        *(uint2*)(sm + off) = hp;
    }
}

// two k16 steps of single-pass fp16 MMA over a 64x32 warp tile
__device__ __forceinline__ void mma_half(uint32_t Ab, uint32_t Bb, int kk0,
                                         int wm, int wn, int lane,
                                         float (&acc)[4][4][4]) {
    #pragma unroll
    for (int ks = 0; ks < 2; ks++) {
        int kk = kk0 + ks * 16;
        uint32_t ah[4][4], bh[4][2];
        int lrow = lane & 15;
        int au = (kk >> 3) + (lane >> 4);          // A smem unit
        #pragma unroll
        for (int mi = 0; mi < 4; mi++) {
            int r = wm * 64 + mi * 16 + lrow;
            uint32_t ad = Ab + r * 128 + ((au ^ (r & 7)) << 4);
            ldsm4(ah[mi], ad);
        }
        int bu = (kk >> 3) + ((lane >> 3) & 1);    // B smem unit
        #pragma unroll
        for (int bi = 0; bi < 2; bi++) {
            int nr = wn * 32 + bi * 16 + ((lane >> 4) << 3) + (lane & 7);
            uint32_t bd = Bb + nr * 128 + ((bu ^ (nr & 7)) << 4);
            uint32_t t[4];
            ldsm4(t, bd);
            bh[2 * bi][0] = t[0]; bh[2 * bi][1] = t[1];
            bh[2 * bi + 1][0] = t[2]; bh[2 * bi + 1][1] = t[3];
        }
        #pragma unroll
        for (int mi = 0; mi < 4; mi++)
            #pragma unroll
            for (int ni = 0; ni < 4; ni++)
                mma16816(acc[mi][ni], ah[mi], bh[ni]);
    }
}

// B fp32 register loads (8 float4 per thread), gemm1 variant (gate|up)
__device__ __forceinline__ void ldg_B1(float4* br, const float* __restrict__ gwB,
                                       const float* __restrict__ uwB, int k0, int tid) {
    #pragma unroll
    for (int i = 0; i < 8; i++) {
        int flat = tid + (i << 8);
        int row = flat >> 4, c4 = flat & 15;
        const float* s = (row < 64) ? (gwB + (size_t)row * HDIM)
                                    : (uwB + (size_t)(row - 64) * HDIM);
        br[i] = *(const float4*)(s + k0 + c4 * 4);
    }
}
// gemm2 variant (down_w)
__device__ __forceinline__ void ldg_B2(float4* br, const float* __restrict__ dwB,
                                       int k0, int tid) {
    #pragma unroll
    for (int i = 0; i < 8; i++) {
        int flat = tid + (i << 8);
        int row = flat >> 4, c4 = flat & 15;
        br[i] = *(const float4*)(dwB + (size_t)row * FDIM + k0 + c4 * 4);
    }
}

// ---------------- kernel 3: gate/up GEMM (mbarrier pipeline) + SiLU ----------------
// 256 threads, all dual-role; producer burst hidden between MMA halves
__global__ void __launch_bounds__(256, 1) gemm1_kernel(const float* __restrict__ gw,
                                                       const float* __restrict__ uw) {
    extern __shared__ char sm[];
    uint32_t sb = smem_u32(sm);
    int e = blockIdx.z;
    int cnt = g_cnt[e];
    int m0 = blockIdx.x << 7;
    if (m0 >= cnt) return;
    int n0f = blockIdx.y << 6;
    int tid = threadIdx.x, lane = tid & 31, wid = tid >> 5;
    int wm = wid & 1, wn = wid >> 1;
    const int NC = HDIM / 64;   // 32

    if (tid == 0) {
        #pragma unroll
        for (int s = 0; s < NST; s++) {
            MBAR_INIT(BAR_FULL(sb, s), 512);   // 256 noinc cp.async arrives + 256 sts arrives
            MBAR_INIT(BAR_EMPTY(sb, s), 8);    // 8 consuming warps
        }
    }
    __syncthreads();

    const __half* A = g_gah + ((size_t)e * T_TOK + m0) * HDIM;
    const float* gwB = gw + ((size_t)e * FDIM + n0f) * HDIM;
    const float* uwB = uw + ((size_t)e * FDIM + n0f) * HDIM;

    float acc[4][4][4];
    #pragma unroll
    for (int a = 0; a < 4; a++)
        #pragma unroll
        for (int b = 0; b < 4; b++)
            #pragma unroll
            for (int c = 0; c < 4; c++) acc[a][b][c] = 0.f;

    float4 br[8];
    ldg_B1(br, gwB, uwB, 0, tid);

    int ps = 0, pph = 1;   // producer cursor
    int cs = 0, cph = 0;   // consumer cursor
    for (int c = 0; c < NC + 2; c++) {
        uint32_t Ab = sb + cs * STGSZ;
        uint32_t Bb = Ab + 16384u;
        if (c >= 2) {
            MBAR_WAIT(BAR_FULL(sb, cs), cph);
            mma_half(Ab, Bb, 0, wm, wn, lane, acc);
        }
        if (c < NC) {
            MBAR_WAIT(BAR_EMPTY(sb, ps), pph);
            uint32_t base = sb + ps * STGSZ;
            cpa_tileA(base, A, HDIM, c << 6, tid);
            MBAR_CPA_ARRIVE(BAR_FULL(sb, ps));
            sts_B<true>(sm, ps * STGSZ + 16384u, br, tid);
            MBAR_ARRIVE(BAR_FULL(sb, ps));
            if (++ps == NST) { ps = 0; pph ^= 1; }
            if (c + 1 < NC) ldg_B1(br, gwB, uwB, (c + 1) << 6, tid);
        }
        if (c >= 2) {
            mma_half(Ab, Bb, 32, wm, wn, lane, acc);
            __syncwarp();
            if (lane == 0) MBAR_ARRIVE(BAR_EMPTY(sb, cs));
            if (++cs == NST) { cs = 0; cph ^= 1; }
        }
    }

    // epilogue: cols 2j/2j+1 = (gate_j, up_j); h = silu(g)*u -> fp16
    #pragma unroll
    for (int mi = 0; mi < 4; mi++)
        #pragma unroll
        for (int rh = 0; rh < 2; rh++) {
            int row = wm * 64 + mi * 16 + (lane >> 2) + rh * 8;
            int slot = m0 + row;
            if (slot < cnt) {
                size_t hb = ((size_t)e * T_TOK + slot) * FDIM + n0f;
                #pragma unroll
                for (int ni = 0; ni < 4; ni++) {
                    float g = acc[mi][ni][rh * 2 + 0];
                    float u = acc[mi][ni][rh * 2 + 1];
                    float h = u * g / (1.f + __expf(-g));
                    int j = wn * 16 + ni * 4 + (lane & 3);
                    g_hbh[hb + j] = __float2half_rn(h);
                }
            }
        }
}

// ---------------- kernel 4: down GEMM (mbarrier pipeline) + weighted scatter ----------------
__global__ void __launch_bounds__(256, 1) gemm2_kernel(const float* __restrict__ dw,
                                                       float* __restrict__ out) {
    extern __shared__ char sm[];
    uint32_t sb = smem_u32(sm);
    int e = blockIdx.z;
    int cnt = g_cnt[e];
    int m0 = blockIdx.x << 7;
    if (m0 >= cnt) return;
    int n0 = blockIdx.y << 7;
    int tid = threadIdx.x, lane = tid & 31, wid = tid >> 5;
    int wm = wid & 1, wn = wid >> 1;
    const int NC = FDIM / 64;   // 86

    if (tid == 0) {
        #pragma unroll
        for (int s = 0; s < NST; s++) {
            MBAR_INIT(BAR_FULL(sb, s), 512);
            MBAR_INIT(BAR_EMPTY(sb, s), 8);
        }
    }
    __syncthreads();

    const __half* A = g_hbh + ((size_t)e * T_TOK + m0) * FDIM;
    const float* dwB = dw + ((size_t)e * HDIM + n0) * FDIM;

    float acc[4][4][4];
    #pragma unroll
    for (int a = 0; a < 4; a++)
        #pragma unroll
        for (int b = 0; b < 4; b++)
            #pragma unroll
            for (int c = 0; c < 4; c++) acc[a][b][c] = 0.f;

    float4 br[8];
    ldg_B2(br, dwB, 0, tid);

    int ps = 0, pph = 1;
    int cs = 0, cph = 0;
    for (int c = 0; c < NC + 2; c++) {
        uint32_t Ab = sb + cs * STGSZ;
        uint32_t Bb = Ab + 16384u;
        if (c >= 2) {
            MBAR_WAIT(BAR_FULL(sb, cs), cph);
            mma_half(Ab, Bb, 0, wm, wn, lane, acc);
        }
        if (c < NC) {
            MBAR_WAIT(BAR_EMPTY(sb, ps), pph);
            uint32_t base = sb + ps * STGSZ;
            cpa_tileA(base, A, FDIM, c << 6, tid);
            MBAR_CPA_ARRIVE(BAR_FULL(sb, ps));
            sts_B<false>(sm, ps * STGSZ + 16384u, br, tid);
            MBAR_ARRIVE(BAR_FULL(sb, ps));
            if (++ps == NST) { ps = 0; pph ^= 1; }
            if (c + 1 < NC) ldg_B2(br, dwB, (c + 1) << 6, tid);
        }
        if (c >= 2) {
            mma_half(Ab, Bb, 32, wm, wn, lane, acc);
            __syncwarp();
            if (lane == 0) MBAR_ARRIVE(BAR_EMPTY(sb, cs));
            if (++cs == NST) { cs = 0; cph ^= 1; }
        }
    }

    // epilogue: weighted atomic scatter to out
    #pragma unroll
    for (int mi = 0; mi < 4; mi++)
        #pragma unroll
        for (int rh = 0; rh < 2; rh++) {
            int row = wm * 64 + mi * 16 + (lane >> 2) + rh * 8;
            int slot = m0 + row;
            if (slot < cnt) {
                int tok = g_ptok[e * T_TOK + slot];
                float w = g_pw[e * T_TOK + slot];
                float* orow = out + (size_t)tok * HDIM + n0;
                #pragma unroll
                for (int ni = 0; ni < 4; ni++) {
                    int col = wn * 32 + ni * 8 + 2 * (lane & 3);
                    atomicAdd(orow + col,     acc[mi][ni][rh * 2 + 0] * w);
                    atomicAdd(orow + col + 1, acc[mi][ni][rh * 2 + 1] * w);
                }
            }
        }
}

// ---------------- launch ----------------
extern "C" void kernel_launch(void* const* d_in, const int* in_sizes, int n_in,
                              void* d_out, int out_size) {
    const float* x  = (const float*)d_in[0];   // [B,S,H]
    const float* rw = (const float*)d_in[1];   // [E,H]
    const float* gw = (const float*)d_in[2];   // [E,F,H]
    const float* uw = (const float*)d_in[3];   // [E,F,H]
    const float* dw = (const float*)d_in[4];   // [E,H,F]
    float* out = (float*)d_out;

    cudaFuncSetAttribute(gemm1_kernel, cudaFuncAttributeMaxDynamicSharedMemorySize, SMEM_GEMM);
    cudaFuncSetAttribute(gemm2_kernel, cudaFuncAttributeMaxDynamicSharedMemorySize, SMEM_GEMM);

    cudaMemsetAsync(out, 0, (size_t)out_size * sizeof(float));
    zero_cnt_kernel<<<1, 32>>>();
    router_kernel<<<T_TOK, 256>>>(x, rw);
    gather_x_kernel<<<EEXP * T_TOK, 128>>>(x);
    gemm1_kernel<<<dim3(16, FDIM / 64, EEXP), 256, SMEM_GEMM>>>(gw, uw);
    gemm2_kernel<<<dim3(16, HDIM / 128, EEXP), 256, SMEM_GEMM>>>(dw, out);
}